// round 2
// baseline (speedup 1.0000x reference)
#include <cuda_runtime.h>

#define SCALE 0.08838834764831845f
#define NEGV  -10000000.0f

// scratch (device globals -- no allocation allowed)
__device__ float g_q  [4L*16384*128];  // [B][HW][C]
__device__ float g_k  [4L*1024*128];   // [B][K][C]
__device__ float g_v  [4L*1024*128];   // [B][K][C]
__device__ float g_ctx[4L*16384*128];  // [B][HW][C]

__device__ __forceinline__ float dot4(float4 a, float4 b){
  return a.x*b.x + a.y*b.y + a.z*b.z + a.w*b.w;
}

// ---------------------------------------------------------------------------
// Fused (1 or 2) x [1x1 conv + BN + ReLU]. in: [B][128][NP] (channel-major),
// out: [B][NP][128] (pixel-major rows). 64 pixels per CTA, 256 threads.
// ---------------------------------------------------------------------------
template<bool TWO>
__global__ __launch_bounds__(256) void proj_kernel(
    const float* __restrict__ in, int NP,
    const float* __restrict__ W1, const float* __restrict__ s1, const float* __restrict__ b1,
    const float* __restrict__ W2, const float* __restrict__ s2, const float* __restrict__ b2,
    float* __restrict__ out)
{
  extern __shared__ float sm[];
  float* xs  = sm;                                   // [64][132]
  float* hs  = sm + 64*132;                          // [64][132] (TWO only)
  float* w1s = sm + 64*132 + (TWO ? 64*132 : 0);     // [128][128]
  float* w2s = w1s + 128*128;                        // [128][128] (TWO only)
  const int tid = threadIdx.x;
  const int b   = blockIdx.y;
  const int p0  = blockIdx.x * 64;

  { const float4* W14=(const float4*)W1; float4* d=(float4*)w1s;
    for (int i=tid;i<4096;i+=256) d[i]=W14[i]; }
  if (TWO) {
    const float4* W24=(const float4*)W2; float4* d=(float4*)w2s;
    for (int i=tid;i<4096;i+=256) d[i]=W24[i];
  }
  { const float* base = in + (size_t)b*128*NP + p0;
    for (int i=tid;i<2048;i+=256){
      int c = i>>4, p4 = (i&15)<<2;
      float4 v = *(const float4*)(base + (size_t)c*NP + p4);
      xs[(p4+0)*132+c]=v.x; xs[(p4+1)*132+c]=v.y;
      xs[(p4+2)*132+c]=v.z; xs[(p4+3)*132+c]=v.w;
    } }
  __syncthreads();

  const int p = tid & 63, og = tid >> 6;   // og covers outputs og*32..og*32+31
  float acc[32];
#pragma unroll
  for (int i=0;i<32;++i) acc[i]=0.f;
  {
    const float4* xr = (const float4*)(xs + p*132);
    const float4* wr = (const float4*)w1s + og*32*32;
    for (int c4=0;c4<32;++c4){
      float4 x = xr[c4];
#pragma unroll
      for (int oi=0;oi<32;++oi) acc[oi] += dot4(x, wr[oi*32+c4]);
    }
  }
  if (TWO) {
#pragma unroll
    for (int oi=0;oi<32;++oi){
      int o = og*32+oi;
      hs[p*132+o] = fmaxf(fmaf(acc[oi], __ldg(s1+o), __ldg(b1+o)), 0.f);
    }
    __syncthreads();
#pragma unroll
    for (int i=0;i<32;++i) acc[i]=0.f;
    const float4* xr = (const float4*)(hs + p*132);
    const float4* wr = (const float4*)w2s + og*32*32;
    for (int c4=0;c4<32;++c4){
      float4 x = xr[c4];
#pragma unroll
      for (int oi=0;oi<32;++oi) acc[oi] += dot4(x, wr[oi*32+c4]);
    }
  }
  const float* ss = TWO ? s2 : s1;
  const float* bs = TWO ? b2 : b1;
  float* orow = out + ((size_t)b*NP + p0 + p)*128 + og*32;
#pragma unroll
  for (int oi=0;oi<32;oi+=4){
    int o = og*32+oi;
    float4 v;
    v.x = fmaxf(fmaf(acc[oi+0], __ldg(ss+o+0), __ldg(bs+o+0)), 0.f);
    v.y = fmaxf(fmaf(acc[oi+1], __ldg(ss+o+1), __ldg(bs+o+1)), 0.f);
    v.z = fmaxf(fmaf(acc[oi+2], __ldg(ss+o+2), __ldg(bs+o+2)), 0.f);
    v.w = fmaxf(fmaf(acc[oi+3], __ldg(ss+o+3), __ldg(bs+o+3)), 0.f);
    *(float4*)(orow+oi) = v;
  }
}

// ---------------------------------------------------------------------------
// Flash-style attention. 64 queries / CTA (8 warps x 8 queries), K streamed
// in 8 chunks of 128 keys. q,k,v row-major [pixel][128]. ctx out row-major.
// mask is int32 (bool serialized as int32 by the harness).
// ---------------------------------------------------------------------------
__global__ __launch_bounds__(256) void attn_kernel(
    const float* __restrict__ q, const float* __restrict__ k,
    const float* __restrict__ v, const int* __restrict__ mask,
    float* __restrict__ ctx)
{
  extern __shared__ float sm[];
  float* qs = sm;              // [64][132]
  float* ks = qs + 64*132;     // [128][132]
  float* vs = ks + 128*132;    // [128][132]
  float* ps = vs + 128*132;    // [64][132]
  const int tid=threadIdx.x, lane=tid&31, w=tid>>5;
  const int b=blockIdx.y, q0=blockIdx.x*64, qb=w*8;

  { const float4* qg=(const float4*)(q + ((size_t)b*16384 + q0)*128);
    float4* d=(float4*)qs;
    for(int i=tid;i<2048;i+=256){ int r=i>>5,c4=i&31; d[r*33+c4]=qg[i]; } }

  float m[8], l[8]; float4 a4[8];
#pragma unroll
  for(int i=0;i<8;++i){ m[i]=-3.0e38f; l[i]=0.f; a4[i]=make_float4(0.f,0.f,0.f,0.f); }

  for(int kb=0;kb<8;++kb){
    const int j0=kb*128;
    __syncthreads();
    { const float4* kg=(const float4*)(k + ((size_t)b*1024 + j0)*128);
      const float4* vg=(const float4*)(v + ((size_t)b*1024 + j0)*128);
      float4* kd=(float4*)ks; float4* vd=(float4*)vs;
      for(int i=tid;i<4096;i+=256){ int r=i>>5,c4=i&31;
        kd[r*33+c4]=kg[i]; vd[r*33+c4]=vg[i]; } }
    __syncthreads();

    bool mb0 = mask[b*1024+j0+lane     ]!=0;
    bool mb1 = mask[b*1024+j0+32+lane  ]!=0;
    bool mb2 = mask[b*1024+j0+64+lane  ]!=0;
    bool mb3 = mask[b*1024+j0+96+lane  ]!=0;

    float s[8][4];
#pragma unroll
    for(int qi=0;qi<8;++qi){ s[qi][0]=0.f;s[qi][1]=0.f;s[qi][2]=0.f;s[qi][3]=0.f; }
    { const float4* ks4=(const float4*)ks;
      const float4* qw=(const float4*)(qs + qb*132);
      for(int c4=0;c4<32;++c4){
        float4 k0=ks4[(lane    )*33+c4];
        float4 k1=ks4[(lane+32 )*33+c4];
        float4 k2=ks4[(lane+64 )*33+c4];
        float4 k3=ks4[(lane+96 )*33+c4];
#pragma unroll
        for(int qi=0;qi<8;++qi){
          float4 qv=qw[qi*33+c4];
          s[qi][0]+=dot4(qv,k0); s[qi][1]+=dot4(qv,k1);
          s[qi][2]+=dot4(qv,k2); s[qi][3]+=dot4(qv,k3);
        }
      }
    }
#pragma unroll
    for(int qi=0;qi<8;++qi){
      s[qi][0] = mb0 ? s[qi][0]*SCALE : NEGV;
      s[qi][1] = mb1 ? s[qi][1]*SCALE : NEGV;
      s[qi][2] = mb2 ? s[qi][2]*SCALE : NEGV;
      s[qi][3] = mb3 ? s[qi][3]*SCALE : NEGV;
      float mx = fmaxf(fmaxf(s[qi][0],s[qi][1]),fmaxf(s[qi][2],s[qi][3]));
#pragma unroll
      for(int off=16;off;off>>=1) mx=fmaxf(mx,__shfl_xor_sync(0xffffffffu,mx,off));
      float mnew = fmaxf(m[qi],mx);
      float alpha = __expf(m[qi]-mnew);
      m[qi]=mnew;
      float e0=__expf(s[qi][0]-mnew), e1=__expf(s[qi][1]-mnew);
      float e2=__expf(s[qi][2]-mnew), e3=__expf(s[qi][3]-mnew);
      float ls=e0+e1+e2+e3;
#pragma unroll
      for(int off=16;off;off>>=1) ls+=__shfl_xor_sync(0xffffffffu,ls,off);
      l[qi]=l[qi]*alpha+ls;
      a4[qi].x*=alpha; a4[qi].y*=alpha; a4[qi].z*=alpha; a4[qi].w*=alpha;
      float* pr = ps + (qb+qi)*132 + lane;
      pr[0]=e0; pr[32]=e1; pr[64]=e2; pr[96]=e3;
    }
    __syncwarp();
    { const float4* vs4=(const float4*)vs;
      for(int j=0;j<128;++j){
        float4 vv = vs4[j*33 + lane];
        float pv[8];
#pragma unroll
        for(int qi=0;qi<8;++qi) pv[qi]=ps[(qb+qi)*132+j];
#pragma unroll
        for(int qi=0;qi<8;++qi){
          a4[qi].x += pv[qi]*vv.x;
          a4[qi].y += pv[qi]*vv.y;
          a4[qi].z += pv[qi]*vv.z;
          a4[qi].w += pv[qi]*vv.w;
        }
      }
    }
    __syncwarp();
  }
#pragma unroll
  for(int qi=0;qi<8;++qi){
    float inv = 1.f/l[qi];
    float4 o = a4[qi];
    o.x*=inv; o.y*=inv; o.z*=inv; o.w*=inv;
    ((float4*)(ctx + ((size_t)b*16384 + q0 + qb + qi)*128))[lane] = o;
  }
}

// ---------------------------------------------------------------------------
// Fused out_project (Wo conv-bn-relu) + bottleneck (Wb 256x256 conv-bn-relu
// over concat(ctxo, query_feats)). Output [B][256][HW]. 64 pixels / CTA.
// ---------------------------------------------------------------------------
__global__ __launch_bounds__(256) void out_kernel(
    const float* __restrict__ ctxin, const float* __restrict__ qf,
    const float* __restrict__ Wo, const float* __restrict__ so, const float* __restrict__ bo,
    const float* __restrict__ Wb, const float* __restrict__ sb, const float* __restrict__ bb,
    float* __restrict__ out)
{
  extern __shared__ float sm[];
  float* cat = sm;             // [64][260]: cols 0..127 = ctxo, 128..255 = qfeat
  float* ws  = cat + 64*260;   // 16384 floats (Wo, then Wb slices)
  float* ci  = ws + 16384;     // [64][132] ctx input
  const int tid=threadIdx.x;
  const int b=blockIdx.y, p0=blockIdx.x*64;

  { const float4* cg=(const float4*)(ctxin + ((size_t)b*16384+p0)*128);
    float4* d=(float4*)ci;
    for(int i=tid;i<2048;i+=256){ int r=i>>5,c4=i&31; d[r*33+c4]=cg[i]; } }
  { const float4* W4=(const float4*)Wo; float4* d=(float4*)ws;
    for(int i=tid;i<4096;i+=256) d[i]=W4[i]; }
  { const float* base = qf + (size_t)b*128*16384 + p0;
    for(int i=tid;i<2048;i+=256){
      int c=i>>4, p4=(i&15)<<2;
      float4 v=*(const float4*)(base + (size_t)c*16384 + p4);
      cat[(p4+0)*260+128+c]=v.x; cat[(p4+1)*260+128+c]=v.y;
      cat[(p4+2)*260+128+c]=v.z; cat[(p4+3)*260+128+c]=v.w;
    } }
  __syncthreads();

  const int p=tid&63, og=tid>>6;
  {  // GEMM1: ctxo = relu(so*(Wo . ctx) + bo) -> cat[p][0..127]
    float acc[32];
#pragma unroll
    for(int i=0;i<32;++i) acc[i]=0.f;
    const float4* xr=(const float4*)(ci + p*132);
    const float4* wr=(const float4*)ws + og*32*32;
    for(int c4=0;c4<32;++c4){
      float4 x=xr[c4];
#pragma unroll
      for(int oi=0;oi<32;++oi) acc[oi]+=dot4(x, wr[oi*32+c4]);
    }
#pragma unroll
    for(int oi=0;oi<32;++oi){
      int o=og*32+oi;
      cat[p*260+o]=fmaxf(fmaf(acc[oi],__ldg(so+o),__ldg(bo+o)),0.f);
    }
  }
  // GEMM2: out = relu(sb*(Wb . cat) + bb), Wb streamed in 4 column slices
  float acc2[64];
#pragma unroll
  for(int i=0;i<64;++i) acc2[i]=0.f;
  for(int cb=0;cb<4;++cb){
    __syncthreads();
    { float4* d=(float4*)ws;
      for(int i=tid;i<4096;i+=256){
        int o=i>>4, c4=i&15;
        d[o*16+c4]=*(const float4*)(Wb + (size_t)o*256 + cb*64 + (c4<<2));
      } }
    __syncthreads();
    const float4* xr=(const float4*)(cat + p*260) + cb*16;
    const float4* wr=(const float4*)ws + og*64*16;
    for(int c4=0;c4<16;++c4){
      float4 x=xr[c4];
#pragma unroll
      for(int oi=0;oi<64;++oi) acc2[oi]+=dot4(x, wr[oi*16+c4]);
    }
  }
  float* ob = out + (size_t)b*256*16384 + p0 + p;
#pragma unroll
  for(int oi=0;oi<64;++oi){
    int o=og*64+oi;
    ob[(size_t)o*16384]=fmaxf(fmaf(acc2[oi],__ldg(sb+o),__ldg(bb+o)),0.f);
  }
}

// ---------------------------------------------------------------------------
extern "C" void kernel_launch(void* const* d_in, const int* in_sizes, int n_in,
                              void* d_out, int out_size)
{
  const float* qfeat=(const float*)d_in[0];
  const float* kfeat=(const float*)d_in[1];
  const float* vfeat=(const float*)d_in[2];
  const int*   kmask=(const int*)d_in[3];
  const float* Wq1=(const float*)d_in[4];  const float* sq1=(const float*)d_in[5];  const float* bq1=(const float*)d_in[6];
  const float* Wq2=(const float*)d_in[7];  const float* sq2=(const float*)d_in[8];  const float* bq2=(const float*)d_in[9];
  const float* Wk1=(const float*)d_in[10]; const float* sk1=(const float*)d_in[11]; const float* bk1=(const float*)d_in[12];
  const float* Wk2=(const float*)d_in[13]; const float* sk2=(const float*)d_in[14]; const float* bk2=(const float*)d_in[15];
  const float* Wv =(const float*)d_in[16]; const float* sv =(const float*)d_in[17]; const float* bv =(const float*)d_in[18];
  const float* Wo =(const float*)d_in[19]; const float* so =(const float*)d_in[20]; const float* bo =(const float*)d_in[21];
  const float* Wb =(const float*)d_in[22]; const float* sb =(const float*)d_in[23]; const float* bb =(const float*)d_in[24];

  float *gq,*gk,*gv,*gc;
  cudaGetSymbolAddress((void**)&gq, g_q);
  cudaGetSymbolAddress((void**)&gk, g_k);
  cudaGetSymbolAddress((void**)&gv, g_v);
  cudaGetSymbolAddress((void**)&gc, g_ctx);

  const int S2 = (64*132*2 + 2*128*128)*4;           // 198,656 B
  const int S1 = (64*132   + 1*128*128)*4;           //  99,328 B
  const int SA = (64*132 + 2*128*132 + 64*132)*4;    // 202,752 B
  const int SO = (64*260 + 16384 + 64*132)*4;        // 165,888 B
  cudaFuncSetAttribute(proj_kernel<true >, cudaFuncAttributeMaxDynamicSharedMemorySize, S2);
  cudaFuncSetAttribute(proj_kernel<false>, cudaFuncAttributeMaxDynamicSharedMemorySize, S1);
  cudaFuncSetAttribute(attn_kernel,        cudaFuncAttributeMaxDynamicSharedMemorySize, SA);
  cudaFuncSetAttribute(out_kernel,         cudaFuncAttributeMaxDynamicSharedMemorySize, SO);

  proj_kernel<true ><<<dim3(256,4),256,S2>>>(qfeat,16384,Wq1,sq1,bq1,Wq2,sq2,bq2,gq);
  proj_kernel<true ><<<dim3(16, 4),256,S2>>>(kfeat,1024, Wk1,sk1,bk1,Wk2,sk2,bk2,gk);
  proj_kernel<false><<<dim3(16, 4),256,S1>>>(vfeat,1024, Wv, sv, bv, nullptr,nullptr,nullptr,gv);
  attn_kernel<<<dim3(256,4),256,SA>>>(gq,gk,gv,kmask,gc);
  out_kernel <<<dim3(256,4),256,SO>>>(gc,qfeat,Wo,so,bo,Wb,sb,bb,(float*)d_out);
}

// round 7
// speedup vs baseline: 1.5966x; 1.5966x over previous
#include <cuda_runtime.h>
#include <cstdint>

#define SCALE 0.08838834764831845f
#define NEGV  -10000000.0f

// scratch (device globals -- no allocation allowed)
__device__ float g_q  [4L*16384*128];  // [B][HW][C]
__device__ float g_k  [4L*1024*128];   // [B][K][C]
__device__ float g_v  [4L*1024*128];   // [B][K][C]
__device__ float g_ctx[4L*16384*128];  // [B][HW][C]

__device__ __forceinline__ float dot4(float4 a, float4 b){
  return a.x*b.x + a.y*b.y + a.z*b.z + a.w*b.w;
}

__device__ __forceinline__ void mma_tf32(float c[4],
    uint32_t a0, uint32_t a1, uint32_t a2, uint32_t a3,
    uint32_t b0, uint32_t b1){
  asm volatile(
    "mma.sync.aligned.m16n8k8.row.col.f32.tf32.tf32.f32 "
    "{%0,%1,%2,%3}, {%4,%5,%6,%7}, {%8,%9}, {%0,%1,%2,%3};\n"
    : "+f"(c[0]),"+f"(c[1]),"+f"(c[2]),"+f"(c[3])
    : "r"(a0),"r"(a1),"r"(a2),"r"(a3),"r"(b0),"r"(b1));
}

// ---------------------------------------------------------------------------
// Fused (1 or 2) x [1x1 conv + BN + ReLU]. in: [B][128][NP] (channel-major),
// out: [B][NP][128] (pixel-major rows). 64 pixels per CTA, 256 threads.
// ---------------------------------------------------------------------------
template<bool TWO>
__global__ __launch_bounds__(256) void proj_kernel(
    const float* __restrict__ in, int NP,
    const float* __restrict__ W1, const float* __restrict__ s1, const float* __restrict__ b1,
    const float* __restrict__ W2, const float* __restrict__ s2, const float* __restrict__ b2,
    float* __restrict__ out)
{
  extern __shared__ float sm[];
  float* xs  = sm;                                   // [64][132]
  float* hs  = sm + 64*132;                          // [64][132] (TWO only)
  float* w1s = sm + 64*132 + (TWO ? 64*132 : 0);     // [128][128]
  float* w2s = w1s + 128*128;                        // [128][128] (TWO only)
  const int tid = threadIdx.x;
  const int b   = blockIdx.y;
  const int p0  = blockIdx.x * 64;

  { const float4* W14=(const float4*)W1; float4* d=(float4*)w1s;
    for (int i=tid;i<4096;i+=256) d[i]=W14[i]; }
  if (TWO) {
    const float4* W24=(const float4*)W2; float4* d=(float4*)w2s;
    for (int i=tid;i<4096;i+=256) d[i]=W24[i];
  }
  { const float* base = in + (size_t)b*128*NP + p0;
    for (int i=tid;i<2048;i+=256){
      int c = i>>4, p4 = (i&15)<<2;
      float4 v = *(const float4*)(base + (size_t)c*NP + p4);
      xs[(p4+0)*132+c]=v.x; xs[(p4+1)*132+c]=v.y;
      xs[(p4+2)*132+c]=v.z; xs[(p4+3)*132+c]=v.w;
    } }
  __syncthreads();

  const int p = tid & 63, og = tid >> 6;   // og covers outputs og*32..og*32+31
  float acc[32];
#pragma unroll
  for (int i=0;i<32;++i) acc[i]=0.f;
  {
    const float4* xr = (const float4*)(xs + p*132);
    const float4* wr = (const float4*)w1s + og*32*32;
    for (int c4=0;c4<32;++c4){
      float4 x = xr[c4];
#pragma unroll
      for (int oi=0;oi<32;++oi) acc[oi] += dot4(x, wr[oi*32+c4]);
    }
  }
  if (TWO) {
#pragma unroll
    for (int oi=0;oi<32;++oi){
      int o = og*32+oi;
      hs[p*132+o] = fmaxf(fmaf(acc[oi], __ldg(s1+o), __ldg(b1+o)), 0.f);
    }
    __syncthreads();
#pragma unroll
    for (int i=0;i<32;++i) acc[i]=0.f;
    const float4* xr = (const float4*)(hs + p*132);
    const float4* wr = (const float4*)w2s + og*32*32;
    for (int c4=0;c4<32;++c4){
      float4 x = xr[c4];
#pragma unroll
      for (int oi=0;oi<32;++oi) acc[oi] += dot4(x, wr[oi*32+c4]);
    }
  }
  const float* ss = TWO ? s2 : s1;
  const float* bs = TWO ? b2 : b1;
  float* orow = out + ((size_t)b*NP + p0 + p)*128 + og*32;
#pragma unroll
  for (int oi=0;oi<32;oi+=4){
    int o = og*32+oi;
    float4 v;
    v.x = fmaxf(fmaf(acc[oi+0], __ldg(ss+o+0), __ldg(bs+o+0)), 0.f);
    v.y = fmaxf(fmaf(acc[oi+1], __ldg(ss+o+1), __ldg(bs+o+1)), 0.f);
    v.z = fmaxf(fmaf(acc[oi+2], __ldg(ss+o+2), __ldg(bs+o+2)), 0.f);
    v.w = fmaxf(fmaf(acc[oi+3], __ldg(ss+o+3), __ldg(bs+o+3)), 0.f);
    *(float4*)(orow+oi) = v;
  }
}

// ---------------------------------------------------------------------------
// Flash attention on tensor cores (mma.sync m16n8k8 tf32).
// CTA: 256 threads = 8 warps, 128 queries (16/warp). K in 16 chunks of 64.
// q,k,v row-major [pixel][128] fp32. Online softmax on MMA fragments.
// ---------------------------------------------------------------------------
__global__ __launch_bounds__(256) void attn_kernel(
    const float* __restrict__ q, const float* __restrict__ k,
    const float* __restrict__ v, const int* __restrict__ mask,
    float* __restrict__ ctx)
{
  extern __shared__ float sm[];
  float* qs  = sm;               // [128][132]
  float* ks  = qs + 128*132;     // [64][132]
  float* vs  = ks + 64*132;      // [64][136]  (pitch 136 -> conflict-free PV B loads)
  float* ps  = vs + 64*136;      // [128][68]
  float* msk = ps + 128*68;      // [64]
  const int tid=threadIdx.x, lane=tid&31, w=tid>>5;
  const int g=lane>>2, tg=lane&3;
  const int b=blockIdx.y, q0=blockIdx.x*128, qb=w*16;

  { const float4* qg=(const float4*)(q + ((size_t)b*16384 + q0)*128);
    float4* d=(float4*)qs;
    for(int i=tid;i<4096;i+=256){ int r=i>>5,c4=i&31; d[r*33+c4]=qg[i]; } }

  float m0=-3.0e38f,m1=-3.0e38f,l0=0.f,l1=0.f;
  float o[16][4];
#pragma unroll
  for(int nt=0;nt<16;++nt){o[nt][0]=0.f;o[nt][1]=0.f;o[nt][2]=0.f;o[nt][3]=0.f;}

  for(int kb=0;kb<16;++kb){
    const int j0=kb*64;
    __syncthreads();
    { const float4* kg=(const float4*)(k + ((size_t)b*1024 + j0)*128);
      const float4* vg=(const float4*)(v + ((size_t)b*1024 + j0)*128);
      float4* kd=(float4*)ks; float4* vd=(float4*)vs;
      for(int i=tid;i<2048;i+=256){ int r=i>>5,c4=i&31;
        kd[r*33+c4]=kg[i]; vd[r*34+c4]=vg[i]; }
      if (tid<64) msk[tid] = mask[b*1024+j0+tid] ? 1.f : 0.f;
    }
    __syncthreads();

    // ---- S = Q K^T  (16 queries x 64 keys per warp) ----
    float s[8][4];
#pragma unroll
    for(int nt=0;nt<8;++nt){s[nt][0]=0.f;s[nt][1]=0.f;s[nt][2]=0.f;s[nt][3]=0.f;}
#pragma unroll
    for(int kk=0;kk<16;++kk){
      const float* qa = qs + (qb+g)*132 + kk*8 + tg;
      uint32_t a0=__float_as_uint(qa[0]);
      uint32_t a1=__float_as_uint(qa[8*132]);
      uint32_t a2=__float_as_uint(qa[4]);
      uint32_t a3=__float_as_uint(qa[8*132+4]);
#pragma unroll
      for(int nt=0;nt<8;++nt){
        const float* kp = ks + (nt*8+g)*132 + kk*8 + tg;
        mma_tf32(s[nt], a0,a1,a2,a3,
                 __float_as_uint(kp[0]), __float_as_uint(kp[4]));
      }
    }
    // ---- mask + scale + online softmax ----
    float mx0=-3.0e38f, mx1=-3.0e38f;
#pragma unroll
    for(int nt=0;nt<8;++nt){
      float mf0 = msk[nt*8+2*tg], mf1 = msk[nt*8+2*tg+1];
      s[nt][0]=fmaf(s[nt][0]*SCALE,mf0,NEGV*(1.f-mf0));
      s[nt][1]=fmaf(s[nt][1]*SCALE,mf1,NEGV*(1.f-mf1));
      s[nt][2]=fmaf(s[nt][2]*SCALE,mf0,NEGV*(1.f-mf0));
      s[nt][3]=fmaf(s[nt][3]*SCALE,mf1,NEGV*(1.f-mf1));
      mx0=fmaxf(mx0,fmaxf(s[nt][0],s[nt][1]));
      mx1=fmaxf(mx1,fmaxf(s[nt][2],s[nt][3]));
    }
    mx0=fmaxf(mx0,__shfl_xor_sync(0xffffffffu,mx0,1));
    mx0=fmaxf(mx0,__shfl_xor_sync(0xffffffffu,mx0,2));
    mx1=fmaxf(mx1,__shfl_xor_sync(0xffffffffu,mx1,1));
    mx1=fmaxf(mx1,__shfl_xor_sync(0xffffffffu,mx1,2));
    float mn0=fmaxf(m0,mx0), mn1=fmaxf(m1,mx1);
    float al0=__expf(m0-mn0), al1=__expf(m1-mn1);
    m0=mn0; m1=mn1;
    float ls0=0.f, ls1=0.f;
#pragma unroll
    for(int nt=0;nt<8;++nt){
      s[nt][0]=__expf(s[nt][0]-m0); s[nt][1]=__expf(s[nt][1]-m0);
      s[nt][2]=__expf(s[nt][2]-m1); s[nt][3]=__expf(s[nt][3]-m1);
      ls0+=s[nt][0]+s[nt][1]; ls1+=s[nt][2]+s[nt][3];
      *(float2*)(ps + (qb+g)*68   + nt*8+2*tg) = make_float2(s[nt][0],s[nt][1]);
      *(float2*)(ps + (qb+g+8)*68 + nt*8+2*tg) = make_float2(s[nt][2],s[nt][3]);
    }
    ls0+=__shfl_xor_sync(0xffffffffu,ls0,1); ls0+=__shfl_xor_sync(0xffffffffu,ls0,2);
    ls1+=__shfl_xor_sync(0xffffffffu,ls1,1); ls1+=__shfl_xor_sync(0xffffffffu,ls1,2);
    l0=l0*al0+ls0; l1=l1*al1+ls1;
#pragma unroll
    for(int nt=0;nt<16;++nt){ o[nt][0]*=al0; o[nt][1]*=al0; o[nt][2]*=al1; o[nt][3]*=al1; }
    __syncwarp();
    // ---- ctx += P V  (16 queries x 128 channels per warp) ----
#pragma unroll
    for(int kk=0;kk<8;++kk){
      const float* pa = ps + (qb+g)*68 + kk*8 + tg;
      uint32_t a0=__float_as_uint(pa[0]);
      uint32_t a1=__float_as_uint(pa[8*68]);
      uint32_t a2=__float_as_uint(pa[4]);
      uint32_t a3=__float_as_uint(pa[8*68+4]);
#pragma unroll
      for(int nt=0;nt<16;++nt){
        const float* vb = vs + (kk*8+tg)*136 + nt*8+g;
        mma_tf32(o[nt], a0,a1,a2,a3,
                 __float_as_uint(vb[0]), __float_as_uint(vb[4*136]));
      }
    }
    __syncwarp();
  }
  const float inv0=1.f/l0, inv1=1.f/l1;
  float* og0 = ctx + ((size_t)b*16384 + q0 + qb + g)*128;
  float* og1 = og0 + 8*128;
#pragma unroll
  for(int nt=0;nt<16;++nt){
    *(float2*)(og0 + nt*8+2*tg) = make_float2(o[nt][0]*inv0, o[nt][1]*inv0);
    *(float2*)(og1 + nt*8+2*tg) = make_float2(o[nt][2]*inv1, o[nt][3]*inv1);
  }
}

// ---------------------------------------------------------------------------
// Fused out_project (Wo conv-bn-relu) + bottleneck (Wb 256x256 conv-bn-relu
// over concat(ctxo, query_feats)). Output [B][256][HW]. 64 pixels / CTA.
// ---------------------------------------------------------------------------
__global__ __launch_bounds__(256) void out_kernel(
    const float* __restrict__ ctxin, const float* __restrict__ qf,
    const float* __restrict__ Wo, const float* __restrict__ so, const float* __restrict__ bo,
    const float* __restrict__ Wb, const float* __restrict__ sb, const float* __restrict__ bb,
    float* __restrict__ out)
{
  extern __shared__ float sm[];
  float* cat = sm;             // [64][260]: cols 0..127 = ctxo, 128..255 = qfeat
  float* ws  = cat + 64*260;   // 16384 floats (Wo, then Wb slices)
  float* ci  = ws + 16384;     // [64][132] ctx input
  const int tid=threadIdx.x;
  const int b=blockIdx.y, p0=blockIdx.x*64;

  { const float4* cg=(const float4*)(ctxin + ((size_t)b*16384+p0)*128);
    float4* d=(float4*)ci;
    for(int i=tid;i<2048;i+=256){ int r=i>>5,c4=i&31; d[r*33+c4]=cg[i]; } }
  { const float4* W4=(const float4*)Wo; float4* d=(float4*)ws;
    for(int i=tid;i<4096;i+=256) d[i]=W4[i]; }
  { const float* base = qf + (size_t)b*128*16384 + p0;
    for(int i=tid;i<2048;i+=256){
      int c=i>>4, p4=(i&15)<<2;
      float4 v=*(const float4*)(base + (size_t)c*16384 + p4);
      cat[(p4+0)*260+128+c]=v.x; cat[(p4+1)*260+128+c]=v.y;
      cat[(p4+2)*260+128+c]=v.z; cat[(p4+3)*260+128+c]=v.w;
    } }
  __syncthreads();

  const int p=tid&63, og=tid>>6;
  {  // GEMM1: ctxo = relu(so*(Wo . ctx) + bo) -> cat[p][0..127]
    float acc[32];
#pragma unroll
    for(int i=0;i<32;++i) acc[i]=0.f;
    const float4* xr=(const float4*)(ci + p*132);
    const float4* wr=(const float4*)ws + og*32*32;
    for(int c4=0;c4<32;++c4){
      float4 x=xr[c4];
#pragma unroll
      for(int oi=0;oi<32;++oi) acc[oi]+=dot4(x, wr[oi*32+c4]);
    }
#pragma unroll
    for(int oi=0;oi<32;++oi){
      int o=og*32+oi;
      cat[p*260+o]=fmaxf(fmaf(acc[oi],__ldg(so+o),__ldg(bo+o)),0.f);
    }
  }
  // GEMM2: out = relu(sb*(Wb . cat) + bb), Wb streamed in 4 column slices
  float acc2[64];
#pragma unroll
  for(int i=0;i<64;++i) acc2[i]=0.f;
  for(int cb=0;cb<4;++cb){
    __syncthreads();
    { float4* d=(float4*)ws;
      for(int i=tid;i<4096;i+=256){
        int o=i>>4, c4=i&15;
        d[o*16+c4]=*(const float4*)(Wb + (size_t)o*256 + cb*64 + (c4<<2));
      } }
    __syncthreads();
    const float4* xr=(const float4*)(cat + p*260) + cb*16;
    const float4* wr=(const float4*)ws + og*64*16;
    for(int c4=0;c4<16;++c4){
      float4 x=xr[c4];
#pragma unroll
      for(int oi=0;oi<64;++oi) acc2[oi]+=dot4(x, wr[oi*16+c4]);
    }
  }
  float* ob = out + (size_t)b*256*16384 + p0 + p;
#pragma unroll
  for(int oi=0;oi<64;++oi){
    int o=og*64+oi;
    ob[(size_t)o*16384]=fmaxf(fmaf(acc2[oi],__ldg(sb+o),__ldg(bb+o)),0.f);
  }
}

// ---------------------------------------------------------------------------
extern "C" void kernel_launch(void* const* d_in, const int* in_sizes, int n_in,
                              void* d_out, int out_size)
{
  const float* qfeat=(const float*)d_in[0];
  const float* kfeat=(const float*)d_in[1];
  const float* vfeat=(const float*)d_in[2];
  const int*   kmask=(const int*)d_in[3];
  const float* Wq1=(const float*)d_in[4];  const float* sq1=(const float*)d_in[5];  const float* bq1=(const float*)d_in[6];
  const float* Wq2=(const float*)d_in[7];  const float* sq2=(const float*)d_in[8];  const float* bq2=(const float*)d_in[9];
  const float* Wk1=(const float*)d_in[10]; const float* sk1=(const float*)d_in[11]; const float* bk1=(const float*)d_in[12];
  const float* Wk2=(const float*)d_in[13]; const float* sk2=(const float*)d_in[14]; const float* bk2=(const float*)d_in[15];
  const float* Wv =(const float*)d_in[16]; const float* sv =(const float*)d_in[17]; const float* bv =(const float*)d_in[18];
  const float* Wo =(const float*)d_in[19]; const float* so =(const float*)d_in[20]; const float* bo =(const float*)d_in[21];
  const float* Wb =(const float*)d_in[22]; const float* sb =(const float*)d_in[23]; const float* bb =(const float*)d_in[24];

  float *gq,*gk,*gv,*gc;
  cudaGetSymbolAddress((void**)&gq, g_q);
  cudaGetSymbolAddress((void**)&gk, g_k);
  cudaGetSymbolAddress((void**)&gv, g_v);
  cudaGetSymbolAddress((void**)&gc, g_ctx);

  const int S2 = (64*132*2 + 2*128*128)*4;                 // 198,656 B
  const int S1 = (64*132   + 1*128*128)*4;                 //  99,328 B
  const int SA = (128*132 + 64*132 + 64*136 + 128*68 + 64)*4; // 171,264 B
  const int SO = (64*260 + 16384 + 64*132)*4;              // 165,888 B
  cudaFuncSetAttribute(proj_kernel<true >, cudaFuncAttributeMaxDynamicSharedMemorySize, S2);
  cudaFuncSetAttribute(proj_kernel<false>, cudaFuncAttributeMaxDynamicSharedMemorySize, S1);
  cudaFuncSetAttribute(attn_kernel,        cudaFuncAttributeMaxDynamicSharedMemorySize, SA);
  cudaFuncSetAttribute(out_kernel,         cudaFuncAttributeMaxDynamicSharedMemorySize, SO);

  proj_kernel<true ><<<dim3(256,4),256,S2>>>(qfeat,16384,Wq1,sq1,bq1,Wq2,sq2,bq2,gq);
  proj_kernel<true ><<<dim3(16, 4),256,S2>>>(kfeat,1024, Wk1,sk1,bk1,Wk2,sk2,bk2,gk);
  proj_kernel<false><<<dim3(16, 4),256,S1>>>(vfeat,1024, Wv, sv, bv, nullptr,nullptr,nullptr,gv);
  attn_kernel<<<dim3(128,4),256,SA>>>(gq,gk,gv,kmask,gc);
  out_kernel <<<dim3(256,4),256,SO>>>(gc,qfeat,Wo,so,bo,Wb,sb,bb,(float*)d_out);
}

// round 8
// speedup vs baseline: 2.4436x; 1.5305x over previous
#include <cuda_runtime.h>
#include <cstdint>

#define SCALE 0.08838834764831845f
#define NEGV  -10000000.0f

// scratch (device globals -- no allocation allowed)
__device__ float g_q  [4L*16384*128];  // [B][HW][C]
__device__ float g_k  [4L*1024*128];   // [B][K][C]
__device__ float g_v  [4L*1024*128];   // [B][K][C]
__device__ float g_ctx[4L*16384*128];  // [B][HW][C]

__device__ __forceinline__ float dot4(float4 a, float4 b){
  return a.x*b.x + a.y*b.y + a.z*b.z + a.w*b.w;
}

__device__ __forceinline__ void mma_tf32(float c[4],
    uint32_t a0, uint32_t a1, uint32_t a2, uint32_t a3,
    uint32_t b0, uint32_t b1){
  asm volatile(
    "mma.sync.aligned.m16n8k8.row.col.f32.tf32.tf32.f32 "
    "{%0,%1,%2,%3}, {%4,%5,%6,%7}, {%8,%9}, {%0,%1,%2,%3};\n"
    : "+f"(c[0]),"+f"(c[1]),"+f"(c[2]),"+f"(c[3])
    : "r"(a0),"r"(a1),"r"(a2),"r"(a3),"r"(b0),"r"(b1));
}

// ---------------------------------------------------------------------------
// Fused (1 or 2) x [1x1 conv + BN + ReLU]. in: [B][128][NP] (channel-major),
// out: [B][NP][128] (pixel-major rows). 64 pixels per CTA, 256 threads.
// ---------------------------------------------------------------------------
template<bool TWO>
__global__ __launch_bounds__(256) void proj_kernel(
    const float* __restrict__ in, int NP,
    const float* __restrict__ W1, const float* __restrict__ s1, const float* __restrict__ b1,
    const float* __restrict__ W2, const float* __restrict__ s2, const float* __restrict__ b2,
    float* __restrict__ out)
{
  extern __shared__ float sm[];
  float* xs  = sm;                                   // [64][132]
  float* hs  = sm + 64*132;                          // [64][132] (TWO only)
  float* w1s = sm + 64*132 + (TWO ? 64*132 : 0);     // [128][128]
  float* w2s = w1s + 128*128;                        // [128][128] (TWO only)
  const int tid = threadIdx.x;
  const int b   = blockIdx.y;
  const int p0  = blockIdx.x * 64;

  { const float4* W14=(const float4*)W1; float4* d=(float4*)w1s;
    for (int i=tid;i<4096;i+=256) d[i]=W14[i]; }
  if (TWO) {
    const float4* W24=(const float4*)W2; float4* d=(float4*)w2s;
    for (int i=tid;i<4096;i+=256) d[i]=W24[i];
  }
  { const float* base = in + (size_t)b*128*NP + p0;
    for (int i=tid;i<2048;i+=256){
      int c = i>>4, p4 = (i&15)<<2;
      float4 v = *(const float4*)(base + (size_t)c*NP + p4);
      xs[(p4+0)*132+c]=v.x; xs[(p4+1)*132+c]=v.y;
      xs[(p4+2)*132+c]=v.z; xs[(p4+3)*132+c]=v.w;
    } }
  __syncthreads();

  const int p = tid & 63, og = tid >> 6;   // og covers outputs og*32..og*32+31
  float acc[32];
#pragma unroll
  for (int i=0;i<32;++i) acc[i]=0.f;
  {
    const float4* xr = (const float4*)(xs + p*132);
    const float4* wr = (const float4*)w1s + og*32*32;
    for (int c4=0;c4<32;++c4){
      float4 x = xr[c4];
#pragma unroll
      for (int oi=0;oi<32;++oi) acc[oi] += dot4(x, wr[oi*32+c4]);
    }
  }
  if (TWO) {
#pragma unroll
    for (int oi=0;oi<32;++oi){
      int o = og*32+oi;
      hs[p*132+o] = fmaxf(fmaf(acc[oi], __ldg(s1+o), __ldg(b1+o)), 0.f);
    }
    __syncthreads();
#pragma unroll
    for (int i=0;i<32;++i) acc[i]=0.f;
    const float4* xr = (const float4*)(hs + p*132);
    const float4* wr = (const float4*)w2s + og*32*32;
    for (int c4=0;c4<32;++c4){
      float4 x = xr[c4];
#pragma unroll
      for (int oi=0;oi<32;++oi) acc[oi] += dot4(x, wr[oi*32+c4]);
    }
  }
  const float* ss = TWO ? s2 : s1;
  const float* bs = TWO ? b2 : b1;
  float* orow = out + ((size_t)b*NP + p0 + p)*128 + og*32;
#pragma unroll
  for (int oi=0;oi<32;oi+=4){
    int o = og*32+oi;
    float4 v;
    v.x = fmaxf(fmaf(acc[oi+0], __ldg(ss+o+0), __ldg(bs+o+0)), 0.f);
    v.y = fmaxf(fmaf(acc[oi+1], __ldg(ss+o+1), __ldg(bs+o+1)), 0.f);
    v.z = fmaxf(fmaf(acc[oi+2], __ldg(ss+o+2), __ldg(bs+o+2)), 0.f);
    v.w = fmaxf(fmaf(acc[oi+3], __ldg(ss+o+3), __ldg(bs+o+3)), 0.f);
    *(float4*)(orow+oi) = v;
  }
}

// ---------------------------------------------------------------------------
// Flash attention on tensor cores (mma.sync m16n8k8 tf32).
// CTA: 256 threads = 8 warps, 128 queries (16/warp). K in 32 chunks of 32.
// P transposed C-frag -> A-frag via intra-quad shfl (no smem round trip).
// smem 103.5KB -> 2 CTAs/SM.
// ---------------------------------------------------------------------------
__global__ __launch_bounds__(256,2) void attn_kernel(
    const float* __restrict__ q, const float* __restrict__ k,
    const float* __restrict__ v, const int* __restrict__ mask,
    float* __restrict__ ctx)
{
  extern __shared__ float sm[];
  float* qs  = sm;               // [128][132]
  float* ks  = qs + 128*132;     // [32][132]
  float* vs  = ks + 32*132;      // [32][136]  (pitch 136 -> conflict-free PV B loads)
  float* msk = vs + 32*136;      // [1024]
  const int tid=threadIdx.x, lane=tid&31, w=tid>>5;
  const int g=lane>>2, tg=lane&3;
  const int b=blockIdx.y, q0=blockIdx.x*128, qb=w*16;

  { const float4* qg=(const float4*)(q + ((size_t)b*16384 + q0)*128);
    float4* d=(float4*)qs;
    for(int i=tid;i<4096;i+=256){ int r=i>>5,c4=i&31; d[r*33+c4]=qg[i]; } }
  for(int i=tid;i<1024;i+=256) msk[i] = mask[b*1024+i] ? 1.f : 0.f;

  float m0=-3.0e38f,m1=-3.0e38f,l0=0.f,l1=0.f;
  float o[16][4];
#pragma unroll
  for(int nt=0;nt<16;++nt){o[nt][0]=0.f;o[nt][1]=0.f;o[nt][2]=0.f;o[nt][3]=0.f;}

  for(int kb=0;kb<32;++kb){
    const int j0=kb*32;
    __syncthreads();
    { const float4* kg=(const float4*)(k + ((size_t)b*1024 + j0)*128);
      const float4* vg=(const float4*)(v + ((size_t)b*1024 + j0)*128);
      float4* kd=(float4*)ks; float4* vd=(float4*)vs;
      for(int i=tid;i<1024;i+=256){ int r=i>>5,c4=i&31;
        kd[r*33+c4]=kg[i]; vd[r*34+c4]=vg[i]; } }
    __syncthreads();

    // ---- S = Q K^T  (16 queries x 32 keys per warp) ----
    float s[4][4];
#pragma unroll
    for(int nt=0;nt<4;++nt){s[nt][0]=0.f;s[nt][1]=0.f;s[nt][2]=0.f;s[nt][3]=0.f;}
#pragma unroll
    for(int kk=0;kk<16;++kk){
      const float* qa = qs + (qb+g)*132 + kk*8 + tg;
      uint32_t a0=__float_as_uint(qa[0]);
      uint32_t a1=__float_as_uint(qa[8*132]);
      uint32_t a2=__float_as_uint(qa[4]);
      uint32_t a3=__float_as_uint(qa[8*132+4]);
#pragma unroll
      for(int nt=0;nt<4;++nt){
        const float* kp = ks + (nt*8+g)*132 + kk*8 + tg;
        mma_tf32(s[nt], a0,a1,a2,a3,
                 __float_as_uint(kp[0]), __float_as_uint(kp[4]));
      }
    }
    // ---- mask + scale + online softmax ----
    float mx0=-3.0e38f, mx1=-3.0e38f;
#pragma unroll
    for(int nt=0;nt<4;++nt){
      float2 mf = *(const float2*)(msk + j0 + nt*8 + 2*tg);
      s[nt][0]=fmaf(s[nt][0]*SCALE,mf.x,NEGV*(1.f-mf.x));
      s[nt][1]=fmaf(s[nt][1]*SCALE,mf.y,NEGV*(1.f-mf.y));
      s[nt][2]=fmaf(s[nt][2]*SCALE,mf.x,NEGV*(1.f-mf.x));
      s[nt][3]=fmaf(s[nt][3]*SCALE,mf.y,NEGV*(1.f-mf.y));
      mx0=fmaxf(mx0,fmaxf(s[nt][0],s[nt][1]));
      mx1=fmaxf(mx1,fmaxf(s[nt][2],s[nt][3]));
    }
    mx0=fmaxf(mx0,__shfl_xor_sync(0xffffffffu,mx0,1));
    mx0=fmaxf(mx0,__shfl_xor_sync(0xffffffffu,mx0,2));
    mx1=fmaxf(mx1,__shfl_xor_sync(0xffffffffu,mx1,1));
    mx1=fmaxf(mx1,__shfl_xor_sync(0xffffffffu,mx1,2));
    float mn0=fmaxf(m0,mx0), mn1=fmaxf(m1,mx1);
    float al0=__expf(m0-mn0), al1=__expf(m1-mn1);
    m0=mn0; m1=mn1;
    float ls0=0.f, ls1=0.f;
#pragma unroll
    for(int nt=0;nt<4;++nt){
      s[nt][0]=__expf(s[nt][0]-m0); s[nt][1]=__expf(s[nt][1]-m0);
      s[nt][2]=__expf(s[nt][2]-m1); s[nt][3]=__expf(s[nt][3]-m1);
      ls0+=s[nt][0]+s[nt][1]; ls1+=s[nt][2]+s[nt][3];
    }
    ls0+=__shfl_xor_sync(0xffffffffu,ls0,1); ls0+=__shfl_xor_sync(0xffffffffu,ls0,2);
    ls1+=__shfl_xor_sync(0xffffffffu,ls1,1); ls1+=__shfl_xor_sync(0xffffffffu,ls1,2);
    l0=l0*al0+ls0; l1=l1*al1+ls1;
#pragma unroll
    for(int nt=0;nt<16;++nt){ o[nt][0]*=al0; o[nt][1]*=al0; o[nt][2]*=al1; o[nt][3]*=al1; }

    // ---- ctx += P V : C-frag -> A-frag via intra-quad shfl ----
    const int srcA = (lane & 28) | (tg>>1);
    const int srcB = srcA | 2;
    const bool odd = (tg & 1);
#pragma unroll
    for(int kk=0;kk<4;++kk){
      float u0=__shfl_sync(0xffffffffu,s[kk][0],srcA);
      float u1=__shfl_sync(0xffffffffu,s[kk][1],srcA);
      float u2=__shfl_sync(0xffffffffu,s[kk][2],srcA);
      float u3=__shfl_sync(0xffffffffu,s[kk][3],srcA);
      float w0=__shfl_sync(0xffffffffu,s[kk][0],srcB);
      float w1=__shfl_sync(0xffffffffu,s[kk][1],srcB);
      float w2=__shfl_sync(0xffffffffu,s[kk][2],srcB);
      float w3=__shfl_sync(0xffffffffu,s[kk][3],srcB);
      uint32_t a0=__float_as_uint(odd?u1:u0);
      uint32_t a1=__float_as_uint(odd?u3:u2);
      uint32_t a2=__float_as_uint(odd?w1:w0);
      uint32_t a3=__float_as_uint(odd?w3:w2);
#pragma unroll
      for(int nt=0;nt<16;++nt){
        const float* vb = vs + (kk*8+tg)*136 + nt*8+g;
        mma_tf32(o[nt], a0,a1,a2,a3,
                 __float_as_uint(vb[0]), __float_as_uint(vb[4*136]));
      }
    }
  }
  const float inv0=1.f/l0, inv1=1.f/l1;
  float* og0 = ctx + ((size_t)b*16384 + q0 + qb + g)*128;
  float* og1 = og0 + 8*128;
#pragma unroll
  for(int nt=0;nt<16;++nt){
    *(float2*)(og0 + nt*8+2*tg) = make_float2(o[nt][0]*inv0, o[nt][1]*inv0);
    *(float2*)(og1 + nt*8+2*tg) = make_float2(o[nt][2]*inv1, o[nt][3]*inv1);
  }
}

// ---------------------------------------------------------------------------
// Fused out_project + bottleneck, both on tf32 MMA.
// CTA: 256 thr = 8 warps; 64 pixels. warp -> (pixel-tile pt = w&3, out-half oh = w>>2).
// GEMM1: ctxo[64][128] = relu(Wo . ctx);  GEMM2: out[64][256] = relu(Wb . cat).
// ---------------------------------------------------------------------------
__global__ __launch_bounds__(256) void out_kernel(
    const float* __restrict__ ctxin, const float* __restrict__ qf,
    const float* __restrict__ Wo, const float* __restrict__ so, const float* __restrict__ bo,
    const float* __restrict__ Wb, const float* __restrict__ sb, const float* __restrict__ bb,
    float* __restrict__ out)
{
  extern __shared__ float sm[];
  float* cat = sm;             // [64][260]: cols 0..127 = ctxo, 128..255 = qfeat
  float* ws  = cat + 64*260;   // 17408 floats: Wo as [128][132], Wb slices as [256][68]
  float* ci  = ws + 17408;     // [64][132] ctx input
  const int tid=threadIdx.x, lane=tid&31, w=tid>>5;
  const int g=lane>>2, tg=lane&3;
  const int b=blockIdx.y, p0=blockIdx.x*64;
  const int pt=w&3, oh=w>>2;

  { const float4* cg=(const float4*)(ctxin + ((size_t)b*16384+p0)*128);
    float4* d=(float4*)ci;
    for(int i=tid;i<2048;i+=256){ int r=i>>5,c4=i&31; d[r*33+c4]=cg[i]; } }
  { const float4* W4=(const float4*)Wo; float4* d=(float4*)ws;
    for(int i=tid;i<4096;i+=256){ int o=i>>5,c4=i&31; d[o*33+c4]=W4[i]; } }
  { const float* base = qf + (size_t)b*128*16384 + p0;
    for(int i=tid;i<2048;i+=256){
      int c=i>>4, p4=(i&15)<<2;
      float4 v=*(const float4*)(base + (size_t)c*16384 + p4);
      cat[(p4+0)*260+128+c]=v.x; cat[(p4+1)*260+128+c]=v.y;
      cat[(p4+2)*260+128+c]=v.z; cat[(p4+3)*260+128+c]=v.w;
    } }
  __syncthreads();

  // ---- GEMM1: warp computes 16 pixels x 64 outs (oh half) ----
  float s1[8][4];
#pragma unroll
  for(int nt=0;nt<8;++nt){s1[nt][0]=0.f;s1[nt][1]=0.f;s1[nt][2]=0.f;s1[nt][3]=0.f;}
#pragma unroll
  for(int kk=0;kk<16;++kk){
    const float* qa = ci + (pt*16+g)*132 + kk*8 + tg;
    uint32_t a0=__float_as_uint(qa[0]);
    uint32_t a1=__float_as_uint(qa[8*132]);
    uint32_t a2=__float_as_uint(qa[4]);
    uint32_t a3=__float_as_uint(qa[8*132+4]);
#pragma unroll
    for(int nt=0;nt<8;++nt){
      const float* wb = ws + (oh*64+nt*8+g)*132 + kk*8 + tg;
      mma_tf32(s1[nt], a0,a1,a2,a3,
               __float_as_uint(wb[0]), __float_as_uint(wb[4]));
    }
  }
#pragma unroll
  for(int nt=0;nt<8;++nt){
    int oc = oh*64+nt*8+2*tg;
    float2 sc=*(const float2*)(so+oc), bi=*(const float2*)(bo+oc);
    float* c0 = cat + (pt*16+g)*260 + oc;
    float* c1 = cat + (pt*16+g+8)*260 + oc;
    c0[0]=fmaxf(fmaf(s1[nt][0],sc.x,bi.x),0.f);
    c0[1]=fmaxf(fmaf(s1[nt][1],sc.y,bi.y),0.f);
    c1[0]=fmaxf(fmaf(s1[nt][2],sc.x,bi.x),0.f);
    c1[1]=fmaxf(fmaf(s1[nt][3],sc.y,bi.y),0.f);
  }

  // ---- GEMM2: warp computes 16 pixels x 128 outs; Wb in 4 in-slices of 64 ----
  float s2[16][4];
#pragma unroll
  for(int nt=0;nt<16;++nt){s2[nt][0]=0.f;s2[nt][1]=0.f;s2[nt][2]=0.f;s2[nt][3]=0.f;}
  for(int cb=0;cb<4;++cb){
    __syncthreads();
    { float4* d=(float4*)ws;
      const float4* Wb4=(const float4*)Wb;
      for(int i=tid;i<4096;i+=256){
        int oc=i>>4, c4=i&15;
        d[oc*17+c4]=Wb4[oc*64 + cb*16 + c4];
      } }
    __syncthreads();
#pragma unroll
    for(int kk=0;kk<8;++kk){
      const float* qa = cat + (pt*16+g)*260 + cb*64 + kk*8 + tg;
      uint32_t a0=__float_as_uint(qa[0]);
      uint32_t a1=__float_as_uint(qa[8*260]);
      uint32_t a2=__float_as_uint(qa[4]);
      uint32_t a3=__float_as_uint(qa[8*260+4]);
#pragma unroll
      for(int nt=0;nt<16;++nt){
        const float* wb = ws + (oh*128+nt*8+g)*68 + kk*8 + tg;
        mma_tf32(s2[nt], a0,a1,a2,a3,
                 __float_as_uint(wb[0]), __float_as_uint(wb[4]));
      }
    }
  }
  // ---- epilogue: BN+relu, channel-major stores (full 32B sectors) ----
  float* ob = out + (size_t)b*256*16384 + p0 + pt*16 + g;
#pragma unroll
  for(int nt=0;nt<16;++nt){
    int oc = oh*128+nt*8+2*tg;
    float2 sc=*(const float2*)(sb+oc), bi=*(const float2*)(bb+oc);
    ob[(size_t)oc*16384]       = fmaxf(fmaf(s2[nt][0],sc.x,bi.x),0.f);
    ob[(size_t)(oc+1)*16384]   = fmaxf(fmaf(s2[nt][1],sc.y,bi.y),0.f);
    ob[(size_t)oc*16384+8]     = fmaxf(fmaf(s2[nt][2],sc.x,bi.x),0.f);
    ob[(size_t)(oc+1)*16384+8] = fmaxf(fmaf(s2[nt][3],sc.y,bi.y),0.f);
  }
}

// ---------------------------------------------------------------------------
extern "C" void kernel_launch(void* const* d_in, const int* in_sizes, int n_in,
                              void* d_out, int out_size)
{
  const float* qfeat=(const float*)d_in[0];
  const float* kfeat=(const float*)d_in[1];
  const float* vfeat=(const float*)d_in[2];
  const int*   kmask=(const int*)d_in[3];
  const float* Wq1=(const float*)d_in[4];  const float* sq1=(const float*)d_in[5];  const float* bq1=(const float*)d_in[6];
  const float* Wq2=(const float*)d_in[7];  const float* sq2=(const float*)d_in[8];  const float* bq2=(const float*)d_in[9];
  const float* Wk1=(const float*)d_in[10]; const float* sk1=(const float*)d_in[11]; const float* bk1=(const float*)d_in[12];
  const float* Wk2=(const float*)d_in[13]; const float* sk2=(const float*)d_in[14]; const float* bk2=(const float*)d_in[15];
  const float* Wv =(const float*)d_in[16]; const float* sv =(const float*)d_in[17]; const float* bv =(const float*)d_in[18];
  const float* Wo =(const float*)d_in[19]; const float* so =(const float*)d_in[20]; const float* bo =(const float*)d_in[21];
  const float* Wb =(const float*)d_in[22]; const float* sb =(const float*)d_in[23]; const float* bb =(const float*)d_in[24];

  float *gq,*gk,*gv,*gc;
  cudaGetSymbolAddress((void**)&gq, g_q);
  cudaGetSymbolAddress((void**)&gk, g_k);
  cudaGetSymbolAddress((void**)&gv, g_v);
  cudaGetSymbolAddress((void**)&gc, g_ctx);

  const int S2 = (64*132*2 + 2*128*128)*4;                 // 198,656 B
  const int S1 = (64*132   + 1*128*128)*4;                 //  99,328 B
  const int SA = (128*132 + 32*132 + 32*136 + 1024)*4;     // 105,984 B (2 CTAs/SM)
  const int SO = (64*260 + 17408 + 64*132)*4;              // 169,984 B
  cudaFuncSetAttribute(proj_kernel<true >, cudaFuncAttributeMaxDynamicSharedMemorySize, S2);
  cudaFuncSetAttribute(proj_kernel<false>, cudaFuncAttributeMaxDynamicSharedMemorySize, S1);
  cudaFuncSetAttribute(attn_kernel,        cudaFuncAttributeMaxDynamicSharedMemorySize, SA);
  cudaFuncSetAttribute(out_kernel,         cudaFuncAttributeMaxDynamicSharedMemorySize, SO);

  proj_kernel<true ><<<dim3(256,4),256,S2>>>(qfeat,16384,Wq1,sq1,bq1,Wq2,sq2,bq2,gq);
  proj_kernel<true ><<<dim3(16, 4),256,S2>>>(kfeat,1024, Wk1,sk1,bk1,Wk2,sk2,bk2,gk);
  proj_kernel<false><<<dim3(16, 4),256,S1>>>(vfeat,1024, Wv, sv, bv, nullptr,nullptr,nullptr,gv);
  attn_kernel<<<dim3(128,4),256,SA>>>(gq,gk,gv,kmask,gc);
  out_kernel <<<dim3(256,4),256,SO>>>(gc,qfeat,Wo,so,bo,Wb,sb,bb,(float*)d_out);
}

// round 10
// speedup vs baseline: 2.9921x; 1.2245x over previous
#include <cuda_runtime.h>
#include <cstdint>

#define SCALE 0.08838834764831845f
#define NEGV  -10000000.0f

// scratch (device globals -- no allocation allowed)
__device__ float g_q  [4L*16384*128];  // [B][HW][C]
__device__ float g_k  [4L*1024*128];   // [B][K][C]
__device__ float g_v  [4L*1024*128];   // [B][K][C]
__device__ float g_ctx[4L*16384*128];  // [B][HW][C]

__device__ __forceinline__ void mma_tf32(float c[4],
    uint32_t a0, uint32_t a1, uint32_t a2, uint32_t a3,
    uint32_t b0, uint32_t b1){
  asm volatile(
    "mma.sync.aligned.m16n8k8.row.col.f32.tf32.tf32.f32 "
    "{%0,%1,%2,%3}, {%4,%5,%6,%7}, {%8,%9}, {%0,%1,%2,%3};\n"
    : "+f"(c[0]),"+f"(c[1]),"+f"(c[2]),"+f"(c[3])
    : "r"(a0),"r"(a1),"r"(a2),"r"(a3),"r"(b0),"r"(b1));
}

// round-to-nearest tf32 (better than HW truncation)
__device__ __forceinline__ uint32_t f2tf(float x){
  uint32_t r; asm("cvt.rna.tf32.f32 %0, %1;" : "=r"(r) : "f"(x)); return r;
}
// split x = hi + lo (hi tf32-rounded, lo exact fp32 residual)
__device__ __forceinline__ void tfsplit(float x, uint32_t& h, uint32_t& l){
  h = f2tf(x);
  l = __float_as_uint(x - __uint_as_float(h));
}

// ---------------------------------------------------------------------------
// Fused (1 or 2) x [1x1 conv + BN + ReLU] on tf32 MMA.
// in: [B][128][NP] channel-major; out: [B][NP][128] pixel-major.
// 64 pixels/CTA, 256 thr = 8 warps = 4 pixel-tiles x 2 out-halves. 2 CTAs/SM.
// ---------------------------------------------------------------------------
template<bool TWO>
__global__ __launch_bounds__(256,2) void proj_kernel(
    const float* __restrict__ in, int NP,
    const float* __restrict__ W1, const float* __restrict__ s1, const float* __restrict__ b1,
    const float* __restrict__ W2, const float* __restrict__ s2, const float* __restrict__ b2,
    float* __restrict__ out)
{
  extern __shared__ float sm[];
  float* xs = sm;            // [64][132] pixel-major activations (in-place h)
  float* ws = sm + 64*132;   // [128][132] weight buffer (W1 then W2)
  const int tid=threadIdx.x, lane=tid&31, w=tid>>5;
  const int g=lane>>2, tg=lane&3;
  const int b=blockIdx.y, p0=blockIdx.x*64;
  const int pt=w&3, oh=w>>2;

  { const float4* W14=(const float4*)W1; float4* d=(float4*)ws;
    for(int i=tid;i<4096;i+=256){ int o=i>>5,c4=i&31; d[o*33+c4]=W14[i]; } }
  { const float* base = in + (size_t)b*128*NP + p0;
    for (int i=tid;i<2048;i+=256){
      int c = i>>4, p4 = (i&15)<<2;
      float4 v = *(const float4*)(base + (size_t)c*NP + p4);
      xs[(p4+0)*132+c]=v.x; xs[(p4+1)*132+c]=v.y;
      xs[(p4+2)*132+c]=v.z; xs[(p4+3)*132+c]=v.w;
    } }
  __syncthreads();

  float acc[8][4];
#pragma unroll
  for(int nt=0;nt<8;++nt){acc[nt][0]=0.f;acc[nt][1]=0.f;acc[nt][2]=0.f;acc[nt][3]=0.f;}
#pragma unroll
  for(int kk=0;kk<16;++kk){
    const float* qa = xs + (pt*16+g)*132 + kk*8 + tg;
    uint32_t a0=f2tf(qa[0]);
    uint32_t a1=f2tf(qa[8*132]);
    uint32_t a2=f2tf(qa[4]);
    uint32_t a3=f2tf(qa[8*132+4]);
#pragma unroll
    for(int nt=0;nt<8;++nt){
      const float* wb = ws + (oh*64+nt*8+g)*132 + kk*8 + tg;
      mma_tf32(acc[nt], a0,a1,a2,a3, f2tf(wb[0]), f2tf(wb[4]));
    }
  }
  __syncthreads();   // all GEMM1 reads of xs/ws complete

  if (TWO) {
    // BN1+relu -> xs in place
#pragma unroll
    for(int nt=0;nt<8;++nt){
      int oc = oh*64+nt*8+2*tg;
      float2 sc=*(const float2*)(s1+oc), bi=*(const float2*)(b1+oc);
      float* c0 = xs + (pt*16+g)*132 + oc;
      float* c1 = xs + (pt*16+g+8)*132 + oc;
      c0[0]=fmaxf(fmaf(acc[nt][0],sc.x,bi.x),0.f);
      c0[1]=fmaxf(fmaf(acc[nt][1],sc.y,bi.y),0.f);
      c1[0]=fmaxf(fmaf(acc[nt][2],sc.x,bi.x),0.f);
      c1[1]=fmaxf(fmaf(acc[nt][3],sc.y,bi.y),0.f);
    }
    { const float4* W24=(const float4*)W2; float4* d=(float4*)ws;
      for(int i=tid;i<4096;i+=256){ int o=i>>5,c4=i&31; d[o*33+c4]=W24[i]; } }
    __syncthreads();

#pragma unroll
    for(int nt=0;nt<8;++nt){acc[nt][0]=0.f;acc[nt][1]=0.f;acc[nt][2]=0.f;acc[nt][3]=0.f;}
#pragma unroll
    for(int kk=0;kk<16;++kk){
      const float* qa = xs + (pt*16+g)*132 + kk*8 + tg;
      uint32_t a0=f2tf(qa[0]);
      uint32_t a1=f2tf(qa[8*132]);
      uint32_t a2=f2tf(qa[4]);
      uint32_t a3=f2tf(qa[8*132+4]);
#pragma unroll
      for(int nt=0;nt<8;++nt){
        const float* wb = ws + (oh*64+nt*8+g)*132 + kk*8 + tg;
        mma_tf32(acc[nt], a0,a1,a2,a3, f2tf(wb[0]), f2tf(wb[4]));
      }
    }
  }
  const float* ss = TWO ? s2 : s1;
  const float* bs = TWO ? b2 : b1;
  float* o0 = out + ((size_t)b*NP + p0 + pt*16 + g)*128;
  float* o1 = o0 + 8*128;
#pragma unroll
  for(int nt=0;nt<8;++nt){
    int oc = oh*64+nt*8+2*tg;
    float2 sc=*(const float2*)(ss+oc), bi=*(const float2*)(bs+oc);
    *(float2*)(o0+oc) = make_float2(fmaxf(fmaf(acc[nt][0],sc.x,bi.x),0.f),
                                    fmaxf(fmaf(acc[nt][1],sc.y,bi.y),0.f));
    *(float2*)(o1+oc) = make_float2(fmaxf(fmaf(acc[nt][2],sc.x,bi.x),0.f),
                                    fmaxf(fmaf(acc[nt][3],sc.y,bi.y),0.f));
  }
}

// ---------------------------------------------------------------------------
// Flash attention on tensor cores (mma.sync m16n8k8 tf32).
// CTA: 256 threads = 8 warps, 128 queries (16/warp). K in 32 chunks of 32.
// P transposed C-frag -> A-frag via intra-quad shfl. 2 CTAs/SM.
// ---------------------------------------------------------------------------
__global__ __launch_bounds__(256,2) void attn_kernel(
    const float* __restrict__ q, const float* __restrict__ k,
    const float* __restrict__ v, const int* __restrict__ mask,
    float* __restrict__ ctx)
{
  extern __shared__ float sm[];
  float* qs  = sm;               // [128][132]
  float* ks  = qs + 128*132;     // [32][132]
  float* vs  = ks + 32*132;      // [32][136]
  float* msk = vs + 32*136;      // [1024] bias: 0 or NEGV
  const int tid=threadIdx.x, lane=tid&31, w=tid>>5;
  const int g=lane>>2, tg=lane&3;
  const int b=blockIdx.y, q0=blockIdx.x*128, qb=w*16;

  { const float4* qg=(const float4*)(q + ((size_t)b*16384 + q0)*128);
    float4* d=(float4*)qs;
    for(int i=tid;i<4096;i+=256){ int r=i>>5,c4=i&31; d[r*33+c4]=qg[i]; } }
  for(int i=tid;i<1024;i+=256) msk[i] = mask[b*1024+i] ? 0.f : NEGV;

  float m0=-3.0e38f,m1=-3.0e38f,l0=0.f,l1=0.f;
  float o[16][4];
#pragma unroll
  for(int nt=0;nt<16;++nt){o[nt][0]=0.f;o[nt][1]=0.f;o[nt][2]=0.f;o[nt][3]=0.f;}

  for(int kb=0;kb<32;++kb){
    const int j0=kb*32;
    __syncthreads();
    { const float4* kg=(const float4*)(k + ((size_t)b*1024 + j0)*128);
      const float4* vg=(const float4*)(v + ((size_t)b*1024 + j0)*128);
      float4* kd=(float4*)ks; float4* vd=(float4*)vs;
      for(int i=tid;i<1024;i+=256){ int r=i>>5,c4=i&31;
        kd[r*33+c4]=kg[i]; vd[r*34+c4]=vg[i]; } }
    __syncthreads();

    // ---- S = Q K^T ----
    float s[4][4];
#pragma unroll
    for(int nt=0;nt<4;++nt){s[nt][0]=0.f;s[nt][1]=0.f;s[nt][2]=0.f;s[nt][3]=0.f;}
#pragma unroll
    for(int kk=0;kk<16;++kk){
      const float* qa = qs + (qb+g)*132 + kk*8 + tg;
      uint32_t a0=__float_as_uint(qa[0]);
      uint32_t a1=__float_as_uint(qa[8*132]);
      uint32_t a2=__float_as_uint(qa[4]);
      uint32_t a3=__float_as_uint(qa[8*132+4]);
#pragma unroll
      for(int nt=0;nt<4;++nt){
        const float* kp = ks + (nt*8+g)*132 + kk*8 + tg;
        mma_tf32(s[nt], a0,a1,a2,a3,
                 __float_as_uint(kp[0]), __float_as_uint(kp[4]));
      }
    }
    // ---- mask bias + scale + online softmax ----
    float mx0=-3.0e38f, mx1=-3.0e38f;
#pragma unroll
    for(int nt=0;nt<4;++nt){
      float2 bi = *(const float2*)(msk + j0 + nt*8 + 2*tg);
      s[nt][0]=fmaf(s[nt][0],SCALE,bi.x);
      s[nt][1]=fmaf(s[nt][1],SCALE,bi.y);
      s[nt][2]=fmaf(s[nt][2],SCALE,bi.x);
      s[nt][3]=fmaf(s[nt][3],SCALE,bi.y);
      mx0=fmaxf(mx0,fmaxf(s[nt][0],s[nt][1]));
      mx1=fmaxf(mx1,fmaxf(s[nt][2],s[nt][3]));
    }
    mx0=fmaxf(mx0,__shfl_xor_sync(0xffffffffu,mx0,1));
    mx0=fmaxf(mx0,__shfl_xor_sync(0xffffffffu,mx0,2));
    mx1=fmaxf(mx1,__shfl_xor_sync(0xffffffffu,mx1,1));
    mx1=fmaxf(mx1,__shfl_xor_sync(0xffffffffu,mx1,2));
    float mn0=fmaxf(m0,mx0), mn1=fmaxf(m1,mx1);
    float al0=__expf(m0-mn0), al1=__expf(m1-mn1);
    m0=mn0; m1=mn1;
    float ls0=0.f, ls1=0.f;
#pragma unroll
    for(int nt=0;nt<4;++nt){
      s[nt][0]=__expf(s[nt][0]-m0); s[nt][1]=__expf(s[nt][1]-m0);
      s[nt][2]=__expf(s[nt][2]-m1); s[nt][3]=__expf(s[nt][3]-m1);
      ls0+=s[nt][0]+s[nt][1]; ls1+=s[nt][2]+s[nt][3];
    }
    ls0+=__shfl_xor_sync(0xffffffffu,ls0,1); ls0+=__shfl_xor_sync(0xffffffffu,ls0,2);
    ls1+=__shfl_xor_sync(0xffffffffu,ls1,1); ls1+=__shfl_xor_sync(0xffffffffu,ls1,2);
    l0=l0*al0+ls0; l1=l1*al1+ls1;
#pragma unroll
    for(int nt=0;nt<16;++nt){ o[nt][0]*=al0; o[nt][1]*=al0; o[nt][2]*=al1; o[nt][3]*=al1; }

    // ---- ctx += P V : C-frag -> A-frag via intra-quad shfl ----
    const int srcA = (lane & 28) | (tg>>1);
    const int srcB = srcA | 2;
    const bool odd = (tg & 1);
#pragma unroll
    for(int kk=0;kk<4;++kk){
      float u0=__shfl_sync(0xffffffffu,s[kk][0],srcA);
      float u1=__shfl_sync(0xffffffffu,s[kk][1],srcA);
      float u2=__shfl_sync(0xffffffffu,s[kk][2],srcA);
      float u3=__shfl_sync(0xffffffffu,s[kk][3],srcA);
      float w0=__shfl_sync(0xffffffffu,s[kk][0],srcB);
      float w1=__shfl_sync(0xffffffffu,s[kk][1],srcB);
      float w2=__shfl_sync(0xffffffffu,s[kk][2],srcB);
      float w3=__shfl_sync(0xffffffffu,s[kk][3],srcB);
      uint32_t a0=__float_as_uint(odd?u1:u0);
      uint32_t a1=__float_as_uint(odd?u3:u2);
      uint32_t a2=__float_as_uint(odd?w1:w0);
      uint32_t a3=__float_as_uint(odd?w3:w2);
#pragma unroll
      for(int nt=0;nt<16;++nt){
        const float* vb = vs + (kk*8+tg)*136 + nt*8+g;
        mma_tf32(o[nt], a0,a1,a2,a3,
                 __float_as_uint(vb[0]), __float_as_uint(vb[4*136]));
      }
    }
  }
  const float inv0=1.f/l0, inv1=1.f/l1;
  float* og0 = ctx + ((size_t)b*16384 + q0 + qb + g)*128;
  float* og1 = og0 + 8*128;
#pragma unroll
  for(int nt=0;nt<16;++nt){
    *(float2*)(og0 + nt*8+2*tg) = make_float2(o[nt][0]*inv0, o[nt][1]*inv0);
    *(float2*)(og1 + nt*8+2*tg) = make_float2(o[nt][2]*inv1, o[nt][3]*inv1);
  }
}

// ---------------------------------------------------------------------------
// Fused out_project + bottleneck on 3-term tf32 MMA (~fp32 accuracy).
// Weights streamed in 32-in-dim slices; GEMM1 A read directly from gmem ctx.
// 64 pixels/CTA, 256 thr, smem 103.4KB -> 2 CTAs/SM.
// ---------------------------------------------------------------------------
__global__ __launch_bounds__(256,2) void out_kernel(
    const float* __restrict__ ctxin, const float* __restrict__ qf,
    const float* __restrict__ Wo, const float* __restrict__ so, const float* __restrict__ bo,
    const float* __restrict__ Wb, const float* __restrict__ sb, const float* __restrict__ bb,
    float* __restrict__ out)
{
  extern __shared__ float sm[];
  float* cat = sm;             // [64][260]: cols 0..127 = ctxo, 128..255 = qfeat
  float* ws  = cat + 64*260;   // [256][36] weight slice buffer
  const int tid=threadIdx.x, lane=tid&31, w=tid>>5;
  const int g=lane>>2, tg=lane&3;
  const int b=blockIdx.y, p0=blockIdx.x*64;
  const int pt=w&3, oh=w>>2;

  { const float* base = qf + (size_t)b*128*16384 + p0;
    for(int i=tid;i<2048;i+=256){
      int c=i>>4, p4=(i&15)<<2;
      float4 v=*(const float4*)(base + (size_t)c*16384 + p4);
      cat[(p4+0)*260+128+c]=v.x; cat[(p4+1)*260+128+c]=v.y;
      cat[(p4+2)*260+128+c]=v.z; cat[(p4+3)*260+128+c]=v.w;
    } }

  // ---- GEMM1: ctxo = relu(BN(Wo . ctx)); A from gmem, Wo streamed 4x32 ----
  float s1r[8][4];
#pragma unroll
  for(int nt=0;nt<8;++nt){s1r[nt][0]=0.f;s1r[nt][1]=0.f;s1r[nt][2]=0.f;s1r[nt][3]=0.f;}
  const float* actx = ctxin + ((size_t)b*16384 + p0 + pt*16 + g)*128;
  for(int cb=0;cb<4;++cb){
    __syncthreads();
    { const float4* W4=(const float4*)Wo; float4* d=(float4*)ws;
      for(int i=tid;i<1024;i+=256){ int o=i>>3,c4=i&7; d[o*9+c4]=W4[o*32 + cb*8 + c4]; } }
    __syncthreads();
#pragma unroll
    for(int kk=0;kk<4;++kk){
      int co = cb*32 + kk*8 + tg;
      uint32_t ah0,al0,ah1,al1,ah2,al2,ah3,al3;
      tfsplit(__ldg(actx + co),          ah0,al0);
      tfsplit(__ldg(actx + 8*128 + co),  ah1,al1);
      tfsplit(__ldg(actx + co + 4),      ah2,al2);
      tfsplit(__ldg(actx + 8*128 + co + 4), ah3,al3);
#pragma unroll
      for(int nt=0;nt<8;++nt){
        const float* wb = ws + (oh*64+nt*8+g)*36 + kk*8 + tg;
        uint32_t bh0,bl0,bh1,bl1;
        tfsplit(wb[0], bh0,bl0);
        tfsplit(wb[4], bh1,bl1);
        mma_tf32(s1r[nt], ah0,ah1,ah2,ah3, bh0,bh1);
        mma_tf32(s1r[nt], al0,al1,al2,al3, bh0,bh1);
        mma_tf32(s1r[nt], ah0,ah1,ah2,ah3, bl0,bl1);
      }
    }
  }
#pragma unroll
  for(int nt=0;nt<8;++nt){
    int oc = oh*64+nt*8+2*tg;
    float2 sc=*(const float2*)(so+oc), bi=*(const float2*)(bo+oc);
    float* c0 = cat + (pt*16+g)*260 + oc;
    float* c1 = cat + (pt*16+g+8)*260 + oc;
    c0[0]=fmaxf(fmaf(s1r[nt][0],sc.x,bi.x),0.f);
    c0[1]=fmaxf(fmaf(s1r[nt][1],sc.y,bi.y),0.f);
    c1[0]=fmaxf(fmaf(s1r[nt][2],sc.x,bi.x),0.f);
    c1[1]=fmaxf(fmaf(s1r[nt][3],sc.y,bi.y),0.f);
  }

  // ---- GEMM2: out = relu(BN(Wb . cat)); Wb streamed 8x32 ----
  float s2r[16][4];
#pragma unroll
  for(int nt=0;nt<16;++nt){s2r[nt][0]=0.f;s2r[nt][1]=0.f;s2r[nt][2]=0.f;s2r[nt][3]=0.f;}
  for(int cb=0;cb<8;++cb){
    __syncthreads();
    { const float4* W4=(const float4*)Wb; float4* d=(float4*)ws;
      for(int i=tid;i<2048;i+=256){ int o=i>>3,c4=i&7; d[o*9+c4]=W4[o*64 + cb*8 + c4]; } }
    __syncthreads();
#pragma unroll
    for(int kk=0;kk<4;++kk){
      const float* qa = cat + (pt*16+g)*260 + cb*32 + kk*8 + tg;
      uint32_t ah0,al0,ah1,al1,ah2,al2,ah3,al3;
      tfsplit(qa[0],       ah0,al0);
      tfsplit(qa[8*260],   ah1,al1);
      tfsplit(qa[4],       ah2,al2);
      tfsplit(qa[8*260+4], ah3,al3);
#pragma unroll
      for(int nt=0;nt<16;++nt){
        const float* wb = ws + (oh*128+nt*8+g)*36 + kk*8 + tg;
        uint32_t bh0,bl0,bh1,bl1;
        tfsplit(wb[0], bh0,bl0);
        tfsplit(wb[4], bh1,bl1);
        mma_tf32(s2r[nt], ah0,ah1,ah2,ah3, bh0,bh1);
        mma_tf32(s2r[nt], al0,al1,al2,al3, bh0,bh1);
        mma_tf32(s2r[nt], ah0,ah1,ah2,ah3, bl0,bl1);
      }
    }
  }
  // ---- epilogue: BN+relu, channel-major stores ----
  float* ob = out + (size_t)b*256*16384 + p0 + pt*16 + g;
#pragma unroll
  for(int nt=0;nt<16;++nt){
    int oc = oh*128+nt*8+2*tg;
    float2 sc=*(const float2*)(sb+oc), bi=*(const float2*)(bb+oc);
    ob[(size_t)oc*16384]       = fmaxf(fmaf(s2r[nt][0],sc.x,bi.x),0.f);
    ob[(size_t)(oc+1)*16384]   = fmaxf(fmaf(s2r[nt][1],sc.y,bi.y),0.f);
    ob[(size_t)oc*16384+8]     = fmaxf(fmaf(s2r[nt][2],sc.x,bi.x),0.f);
    ob[(size_t)(oc+1)*16384+8] = fmaxf(fmaf(s2r[nt][3],sc.y,bi.y),0.f);
  }
}

// ---------------------------------------------------------------------------
extern "C" void kernel_launch(void* const* d_in, const int* in_sizes, int n_in,
                              void* d_out, int out_size)
{
  const float* qfeat=(const float*)d_in[0];
  const float* kfeat=(const float*)d_in[1];
  const float* vfeat=(const float*)d_in[2];
  const int*   kmask=(const int*)d_in[3];
  const float* Wq1=(const float*)d_in[4];  const float* sq1=(const float*)d_in[5];  const float* bq1=(const float*)d_in[6];
  const float* Wq2=(const float*)d_in[7];  const float* sq2=(const float*)d_in[8];  const float* bq2=(const float*)d_in[9];
  const float* Wk1=(const float*)d_in[10]; const float* sk1=(const float*)d_in[11]; const float* bk1=(const float*)d_in[12];
  const float* Wk2=(const float*)d_in[13]; const float* sk2=(const float*)d_in[14]; const float* bk2=(const float*)d_in[15];
  const float* Wv =(const float*)d_in[16]; const float* sv =(const float*)d_in[17]; const float* bv =(const float*)d_in[18];
  const float* Wo =(const float*)d_in[19]; const float* so =(const float*)d_in[20]; const float* bo =(const float*)d_in[21];
  const float* Wb =(const float*)d_in[22]; const float* sb =(const float*)d_in[23]; const float* bb =(const float*)d_in[24];

  float *gq,*gk,*gv,*gc;
  cudaGetSymbolAddress((void**)&gq, g_q);
  cudaGetSymbolAddress((void**)&gk, g_k);
  cudaGetSymbolAddress((void**)&gv, g_v);
  cudaGetSymbolAddress((void**)&gc, g_ctx);

  const int SP = (64*132 + 128*132)*4;                 // 101,376 B (2 CTAs/SM)
  const int SA = (128*132 + 32*132 + 32*136 + 1024)*4; // 105,984 B (2 CTAs/SM)
  const int SO = (64*260 + 256*36)*4;                  // 103,424 B (2 CTAs/SM)
  cudaFuncSetAttribute(proj_kernel<true >, cudaFuncAttributeMaxDynamicSharedMemorySize, SP);
  cudaFuncSetAttribute(proj_kernel<false>, cudaFuncAttributeMaxDynamicSharedMemorySize, SP);
  cudaFuncSetAttribute(attn_kernel,        cudaFuncAttributeMaxDynamicSharedMemorySize, SA);
  cudaFuncSetAttribute(out_kernel,         cudaFuncAttributeMaxDynamicSharedMemorySize, SO);

  proj_kernel<true ><<<dim3(256,4),256,SP>>>(qfeat,16384,Wq1,sq1,bq1,Wq2,sq2,bq2,gq);
  proj_kernel<true ><<<dim3(16, 4),256,SP>>>(kfeat,1024, Wk1,sk1,bk1,Wk2,sk2,bk2,gk);
  proj_kernel<false><<<dim3(16, 4),256,SP>>>(vfeat,1024, Wv, sv, bv, nullptr,nullptr,nullptr,gv);
  attn_kernel<<<dim3(128,4),256,SA>>>(gq,gk,gv,kmask,gc);
  out_kernel <<<dim3(256,4),256,SO>>>(gc,qfeat,Wo,so,bo,Wb,sb,bb,(float*)d_out);
}

// round 11
// speedup vs baseline: 2.9980x; 1.0020x over previous
#include <cuda_runtime.h>
#include <cstdint>

#define SCALE 0.08838834764831845f
#define NEGV  -10000000.0f

// scratch (device globals -- no allocation allowed)
__device__ float g_q  [4L*16384*128];  // [B][HW][C]
__device__ float g_k  [4L*1024*128];   // [B][K][C]
__device__ float g_v  [4L*1024*128];   // [B][K][C]
__device__ float g_ctx[4L*16384*128];  // [B][HW][C]

__device__ __forceinline__ void mma_tf32(float c[4],
    uint32_t a0, uint32_t a1, uint32_t a2, uint32_t a3,
    uint32_t b0, uint32_t b1){
  asm volatile(
    "mma.sync.aligned.m16n8k8.row.col.f32.tf32.tf32.f32 "
    "{%0,%1,%2,%3}, {%4,%5,%6,%7}, {%8,%9}, {%0,%1,%2,%3};\n"
    : "+f"(c[0]),"+f"(c[1]),"+f"(c[2]),"+f"(c[3])
    : "r"(a0),"r"(a1),"r"(a2),"r"(a3),"r"(b0),"r"(b1));
}

// round-to-nearest tf32 (better than HW truncation)
__device__ __forceinline__ uint32_t f2tf(float x){
  uint32_t r; asm("cvt.rna.tf32.f32 %0, %1;" : "=r"(r) : "f"(x)); return r;
}
// split x = hi + lo (hi tf32-rounded, lo exact fp32 residual)
__device__ __forceinline__ void tfsplit(float x, uint32_t& h, uint32_t& l){
  h = f2tf(x);
  l = __float_as_uint(x - __uint_as_float(h));
}

// ---------------------------------------------------------------------------
// Fused (1 or 2) x [1x1 conv + BN + ReLU] on tf32 MMA.
// in: [B][128][NP] channel-major; out: [B][NP][128] pixel-major.
// 64 pixels/CTA, 256 thr = 8 warps = 4 pixel-tiles x 2 out-halves. 2 CTAs/SM.
// ---------------------------------------------------------------------------
template<bool TWO>
__global__ __launch_bounds__(256,2) void proj_kernel(
    const float* __restrict__ in, int NP,
    const float* __restrict__ W1, const float* __restrict__ s1, const float* __restrict__ b1,
    const float* __restrict__ W2, const float* __restrict__ s2, const float* __restrict__ b2,
    float* __restrict__ out)
{
  extern __shared__ float sm[];
  float* xs = sm;            // [64][132] pixel-major activations (in-place h)
  float* ws = sm + 64*132;   // [128][132] weight buffer (W1 then W2)
  const int tid=threadIdx.x, lane=tid&31, w=tid>>5;
  const int g=lane>>2, tg=lane&3;
  const int b=blockIdx.y, p0=blockIdx.x*64;
  const int pt=w&3, oh=w>>2;

  { const float4* W14=(const float4*)W1; float4* d=(float4*)ws;
    for(int i=tid;i<4096;i+=256){ int o=i>>5,c4=i&31; d[o*33+c4]=W14[i]; } }
  { const float* base = in + (size_t)b*128*NP + p0;
    for (int i=tid;i<2048;i+=256){
      int c = i>>4, p4 = (i&15)<<2;
      float4 v = *(const float4*)(base + (size_t)c*NP + p4);
      xs[(p4+0)*132+c]=v.x; xs[(p4+1)*132+c]=v.y;
      xs[(p4+2)*132+c]=v.z; xs[(p4+3)*132+c]=v.w;
    } }
  __syncthreads();

  float acc[8][4];
#pragma unroll
  for(int nt=0;nt<8;++nt){acc[nt][0]=0.f;acc[nt][1]=0.f;acc[nt][2]=0.f;acc[nt][3]=0.f;}
#pragma unroll
  for(int kk=0;kk<16;++kk){
    const float* qa = xs + (pt*16+g)*132 + kk*8 + tg;
    uint32_t a0=f2tf(qa[0]);
    uint32_t a1=f2tf(qa[8*132]);
    uint32_t a2=f2tf(qa[4]);
    uint32_t a3=f2tf(qa[8*132+4]);
#pragma unroll
    for(int nt=0;nt<8;++nt){
      const float* wb = ws + (oh*64+nt*8+g)*132 + kk*8 + tg;
      mma_tf32(acc[nt], a0,a1,a2,a3, f2tf(wb[0]), f2tf(wb[4]));
    }
  }
  __syncthreads();   // all GEMM1 reads of xs/ws complete

  if (TWO) {
    // BN1+relu -> xs in place
#pragma unroll
    for(int nt=0;nt<8;++nt){
      int oc = oh*64+nt*8+2*tg;
      float2 sc=*(const float2*)(s1+oc), bi=*(const float2*)(b1+oc);
      float* c0 = xs + (pt*16+g)*132 + oc;
      float* c1 = xs + (pt*16+g+8)*132 + oc;
      c0[0]=fmaxf(fmaf(acc[nt][0],sc.x,bi.x),0.f);
      c0[1]=fmaxf(fmaf(acc[nt][1],sc.y,bi.y),0.f);
      c1[0]=fmaxf(fmaf(acc[nt][2],sc.x,bi.x),0.f);
      c1[1]=fmaxf(fmaf(acc[nt][3],sc.y,bi.y),0.f);
    }
    { const float4* W24=(const float4*)W2; float4* d=(float4*)ws;
      for(int i=tid;i<4096;i+=256){ int o=i>>5,c4=i&31; d[o*33+c4]=W24[i]; } }
    __syncthreads();

#pragma unroll
    for(int nt=0;nt<8;++nt){acc[nt][0]=0.f;acc[nt][1]=0.f;acc[nt][2]=0.f;acc[nt][3]=0.f;}
#pragma unroll
    for(int kk=0;kk<16;++kk){
      const float* qa = xs + (pt*16+g)*132 + kk*8 + tg;
      uint32_t a0=f2tf(qa[0]);
      uint32_t a1=f2tf(qa[8*132]);
      uint32_t a2=f2tf(qa[4]);
      uint32_t a3=f2tf(qa[8*132+4]);
#pragma unroll
      for(int nt=0;nt<8;++nt){
        const float* wb = ws + (oh*64+nt*8+g)*132 + kk*8 + tg;
        mma_tf32(acc[nt], a0,a1,a2,a3, f2tf(wb[0]), f2tf(wb[4]));
      }
    }
  }
  const float* ss = TWO ? s2 : s1;
  const float* bs = TWO ? b2 : b1;
  float* o0 = out + ((size_t)b*NP + p0 + pt*16 + g)*128;
  float* o1 = o0 + 8*128;
#pragma unroll
  for(int nt=0;nt<8;++nt){
    int oc = oh*64+nt*8+2*tg;
    float2 sc=*(const float2*)(ss+oc), bi=*(const float2*)(bs+oc);
    *(float2*)(o0+oc) = make_float2(fmaxf(fmaf(acc[nt][0],sc.x,bi.x),0.f),
                                    fmaxf(fmaf(acc[nt][1],sc.y,bi.y),0.f));
    *(float2*)(o1+oc) = make_float2(fmaxf(fmaf(acc[nt][2],sc.x,bi.x),0.f),
                                    fmaxf(fmaf(acc[nt][3],sc.y,bi.y),0.f));
  }
}

// ---------------------------------------------------------------------------
// Flash attention on tensor cores (mma.sync m16n8k8 tf32).
// CTA: 256 threads = 8 warps, 128 queries (16/warp). K in 32 chunks of 32.
// P transposed C-frag -> A-frag via intra-quad shfl. 2 CTAs/SM.
// ---------------------------------------------------------------------------
__global__ __launch_bounds__(256,2) void attn_kernel(
    const float* __restrict__ q, const float* __restrict__ k,
    const float* __restrict__ v, const int* __restrict__ mask,
    float* __restrict__ ctx)
{
  extern __shared__ float sm[];
  float* qs  = sm;               // [128][132]
  float* ks  = qs + 128*132;     // [32][132]
  float* vs  = ks + 32*132;      // [32][136]
  float* msk = vs + 32*136;      // [1024] bias: 0 or NEGV
  const int tid=threadIdx.x, lane=tid&31, w=tid>>5;
  const int g=lane>>2, tg=lane&3;
  const int b=blockIdx.y, q0=blockIdx.x*128, qb=w*16;

  { const float4* qg=(const float4*)(q + ((size_t)b*16384 + q0)*128);
    float4* d=(float4*)qs;
    for(int i=tid;i<4096;i+=256){ int r=i>>5,c4=i&31; d[r*33+c4]=qg[i]; } }
  for(int i=tid;i<1024;i+=256) msk[i] = mask[b*1024+i] ? 0.f : NEGV;

  float m0=-3.0e38f,m1=-3.0e38f,l0=0.f,l1=0.f;
  float o[16][4];
#pragma unroll
  for(int nt=0;nt<16;++nt){o[nt][0]=0.f;o[nt][1]=0.f;o[nt][2]=0.f;o[nt][3]=0.f;}

  for(int kb=0;kb<32;++kb){
    const int j0=kb*32;
    __syncthreads();
    { const float4* kg=(const float4*)(k + ((size_t)b*1024 + j0)*128);
      const float4* vg=(const float4*)(v + ((size_t)b*1024 + j0)*128);
      float4* kd=(float4*)ks; float4* vd=(float4*)vs;
      for(int i=tid;i<1024;i+=256){ int r=i>>5,c4=i&31;
        kd[r*33+c4]=kg[i]; vd[r*34+c4]=vg[i]; } }
    __syncthreads();

    // ---- S = Q K^T ----
    float s[4][4];
#pragma unroll
    for(int nt=0;nt<4;++nt){s[nt][0]=0.f;s[nt][1]=0.f;s[nt][2]=0.f;s[nt][3]=0.f;}
#pragma unroll
    for(int kk=0;kk<16;++kk){
      const float* qa = qs + (qb+g)*132 + kk*8 + tg;
      uint32_t a0=__float_as_uint(qa[0]);
      uint32_t a1=__float_as_uint(qa[8*132]);
      uint32_t a2=__float_as_uint(qa[4]);
      uint32_t a3=__float_as_uint(qa[8*132+4]);
#pragma unroll
      for(int nt=0;nt<4;++nt){
        const float* kp = ks + (nt*8+g)*132 + kk*8 + tg;
        mma_tf32(s[nt], a0,a1,a2,a3,
                 __float_as_uint(kp[0]), __float_as_uint(kp[4]));
      }
    }
    // ---- mask bias + scale + online softmax ----
    float mx0=-3.0e38f, mx1=-3.0e38f;
#pragma unroll
    for(int nt=0;nt<4;++nt){
      float2 bi = *(const float2*)(msk + j0 + nt*8 + 2*tg);
      s[nt][0]=fmaf(s[nt][0],SCALE,bi.x);
      s[nt][1]=fmaf(s[nt][1],SCALE,bi.y);
      s[nt][2]=fmaf(s[nt][2],SCALE,bi.x);
      s[nt][3]=fmaf(s[nt][3],SCALE,bi.y);
      mx0=fmaxf(mx0,fmaxf(s[nt][0],s[nt][1]));
      mx1=fmaxf(mx1,fmaxf(s[nt][2],s[nt][3]));
    }
    mx0=fmaxf(mx0,__shfl_xor_sync(0xffffffffu,mx0,1));
    mx0=fmaxf(mx0,__shfl_xor_sync(0xffffffffu,mx0,2));
    mx1=fmaxf(mx1,__shfl_xor_sync(0xffffffffu,mx1,1));
    mx1=fmaxf(mx1,__shfl_xor_sync(0xffffffffu,mx1,2));
    float mn0=fmaxf(m0,mx0), mn1=fmaxf(m1,mx1);
    float al0=__expf(m0-mn0), al1=__expf(m1-mn1);
    m0=mn0; m1=mn1;
    float ls0=0.f, ls1=0.f;
#pragma unroll
    for(int nt=0;nt<4;++nt){
      s[nt][0]=__expf(s[nt][0]-m0); s[nt][1]=__expf(s[nt][1]-m0);
      s[nt][2]=__expf(s[nt][2]-m1); s[nt][3]=__expf(s[nt][3]-m1);
      ls0+=s[nt][0]+s[nt][1]; ls1+=s[nt][2]+s[nt][3];
    }
    ls0+=__shfl_xor_sync(0xffffffffu,ls0,1); ls0+=__shfl_xor_sync(0xffffffffu,ls0,2);
    ls1+=__shfl_xor_sync(0xffffffffu,ls1,1); ls1+=__shfl_xor_sync(0xffffffffu,ls1,2);
    l0=l0*al0+ls0; l1=l1*al1+ls1;
#pragma unroll
    for(int nt=0;nt<16;++nt){ o[nt][0]*=al0; o[nt][1]*=al0; o[nt][2]*=al1; o[nt][3]*=al1; }

    // ---- ctx += P V : C-frag -> A-frag via intra-quad shfl ----
    const int srcA = (lane & 28) | (tg>>1);
    const int srcB = srcA | 2;
    const bool odd = (tg & 1);
#pragma unroll
    for(int kk=0;kk<4;++kk){
      float u0=__shfl_sync(0xffffffffu,s[kk][0],srcA);
      float u1=__shfl_sync(0xffffffffu,s[kk][1],srcA);
      float u2=__shfl_sync(0xffffffffu,s[kk][2],srcA);
      float u3=__shfl_sync(0xffffffffu,s[kk][3],srcA);
      float w0=__shfl_sync(0xffffffffu,s[kk][0],srcB);
      float w1=__shfl_sync(0xffffffffu,s[kk][1],srcB);
      float w2=__shfl_sync(0xffffffffu,s[kk][2],srcB);
      float w3=__shfl_sync(0xffffffffu,s[kk][3],srcB);
      uint32_t a0=__float_as_uint(odd?u1:u0);
      uint32_t a1=__float_as_uint(odd?u3:u2);
      uint32_t a2=__float_as_uint(odd?w1:w0);
      uint32_t a3=__float_as_uint(odd?w3:w2);
#pragma unroll
      for(int nt=0;nt<16;++nt){
        const float* vb = vs + (kk*8+tg)*136 + nt*8+g;
        mma_tf32(o[nt], a0,a1,a2,a3,
                 __float_as_uint(vb[0]), __float_as_uint(vb[4*136]));
      }
    }
  }
  const float inv0=1.f/l0, inv1=1.f/l1;
  float* og0 = ctx + ((size_t)b*16384 + q0 + qb + g)*128;
  float* og1 = og0 + 8*128;
#pragma unroll
  for(int nt=0;nt<16;++nt){
    *(float2*)(og0 + nt*8+2*tg) = make_float2(o[nt][0]*inv0, o[nt][1]*inv0);
    *(float2*)(og1 + nt*8+2*tg) = make_float2(o[nt][2]*inv1, o[nt][3]*inv1);
  }
}

// ---------------------------------------------------------------------------
// Fused out_project + bottleneck on 3-term tf32 MMA (~fp32 accuracy).
// Weights streamed in 32-in-dim slices; GEMM1 A read directly from gmem ctx.
// 64 pixels/CTA, 256 thr, smem 103.4KB -> 2 CTAs/SM.
// ---------------------------------------------------------------------------
__global__ __launch_bounds__(256,2) void out_kernel(
    const float* __restrict__ ctxin, const float* __restrict__ qf,
    const float* __restrict__ Wo, const float* __restrict__ so, const float* __restrict__ bo,
    const float* __restrict__ Wb, const float* __restrict__ sb, const float* __restrict__ bb,
    float* __restrict__ out)
{
  extern __shared__ float sm[];
  float* cat = sm;             // [64][260]: cols 0..127 = ctxo, 128..255 = qfeat
  float* ws  = cat + 64*260;   // [256][36] weight slice buffer
  const int tid=threadIdx.x, lane=tid&31, w=tid>>5;
  const int g=lane>>2, tg=lane&3;
  const int b=blockIdx.y, p0=blockIdx.x*64;
  const int pt=w&3, oh=w>>2;

  { const float* base = qf + (size_t)b*128*16384 + p0;
    for(int i=tid;i<2048;i+=256){
      int c=i>>4, p4=(i&15)<<2;
      float4 v=*(const float4*)(base + (size_t)c*16384 + p4);
      cat[(p4+0)*260+128+c]=v.x; cat[(p4+1)*260+128+c]=v.y;
      cat[(p4+2)*260+128+c]=v.z; cat[(p4+3)*260+128+c]=v.w;
    } }

  // ---- GEMM1: ctxo = relu(BN(Wo . ctx)); A from gmem, Wo streamed 4x32 ----
  float s1r[8][4];
#pragma unroll
  for(int nt=0;nt<8;++nt){s1r[nt][0]=0.f;s1r[nt][1]=0.f;s1r[nt][2]=0.f;s1r[nt][3]=0.f;}
  const float* actx = ctxin + ((size_t)b*16384 + p0 + pt*16 + g)*128;
  for(int cb=0;cb<4;++cb){
    __syncthreads();
    { const float4* W4=(const float4*)Wo; float4* d=(float4*)ws;
      for(int i=tid;i<1024;i+=256){ int o=i>>3,c4=i&7; d[o*9+c4]=W4[o*32 + cb*8 + c4]; } }
    __syncthreads();
#pragma unroll
    for(int kk=0;kk<4;++kk){
      int co = cb*32 + kk*8 + tg;
      uint32_t ah0,al0,ah1,al1,ah2,al2,ah3,al3;
      tfsplit(__ldg(actx + co),          ah0,al0);
      tfsplit(__ldg(actx + 8*128 + co),  ah1,al1);
      tfsplit(__ldg(actx + co + 4),      ah2,al2);
      tfsplit(__ldg(actx + 8*128 + co + 4), ah3,al3);
#pragma unroll
      for(int nt=0;nt<8;++nt){
        const float* wb = ws + (oh*64+nt*8+g)*36 + kk*8 + tg;
        uint32_t bh0,bl0,bh1,bl1;
        tfsplit(wb[0], bh0,bl0);
        tfsplit(wb[4], bh1,bl1);
        mma_tf32(s1r[nt], ah0,ah1,ah2,ah3, bh0,bh1);
        mma_tf32(s1r[nt], al0,al1,al2,al3, bh0,bh1);
        mma_tf32(s1r[nt], ah0,ah1,ah2,ah3, bl0,bl1);
      }
    }
  }
#pragma unroll
  for(int nt=0;nt<8;++nt){
    int oc = oh*64+nt*8+2*tg;
    float2 sc=*(const float2*)(so+oc), bi=*(const float2*)(bo+oc);
    float* c0 = cat + (pt*16+g)*260 + oc;
    float* c1 = cat + (pt*16+g+8)*260 + oc;
    c0[0]=fmaxf(fmaf(s1r[nt][0],sc.x,bi.x),0.f);
    c0[1]=fmaxf(fmaf(s1r[nt][1],sc.y,bi.y),0.f);
    c1[0]=fmaxf(fmaf(s1r[nt][2],sc.x,bi.x),0.f);
    c1[1]=fmaxf(fmaf(s1r[nt][3],sc.y,bi.y),0.f);
  }

  // ---- GEMM2: out = relu(BN(Wb . cat)); Wb streamed 8x32 ----
  float s2r[16][4];
#pragma unroll
  for(int nt=0;nt<16;++nt){s2r[nt][0]=0.f;s2r[nt][1]=0.f;s2r[nt][2]=0.f;s2r[nt][3]=0.f;}
  for(int cb=0;cb<8;++cb){
    __syncthreads();
    { const float4* W4=(const float4*)Wb; float4* d=(float4*)ws;
      for(int i=tid;i<2048;i+=256){ int o=i>>3,c4=i&7; d[o*9+c4]=W4[o*64 + cb*8 + c4]; } }
    __syncthreads();
#pragma unroll
    for(int kk=0;kk<4;++kk){
      const float* qa = cat + (pt*16+g)*260 + cb*32 + kk*8 + tg;
      uint32_t ah0,al0,ah1,al1,ah2,al2,ah3,al3;
      tfsplit(qa[0],       ah0,al0);
      tfsplit(qa[8*260],   ah1,al1);
      tfsplit(qa[4],       ah2,al2);
      tfsplit(qa[8*260+4], ah3,al3);
#pragma unroll
      for(int nt=0;nt<16;++nt){
        const float* wb = ws + (oh*128+nt*8+g)*36 + kk*8 + tg;
        uint32_t bh0,bl0,bh1,bl1;
        tfsplit(wb[0], bh0,bl0);
        tfsplit(wb[4], bh1,bl1);
        mma_tf32(s2r[nt], ah0,ah1,ah2,ah3, bh0,bh1);
        mma_tf32(s2r[nt], al0,al1,al2,al3, bh0,bh1);
        mma_tf32(s2r[nt], ah0,ah1,ah2,ah3, bl0,bl1);
      }
    }
  }
  // ---- epilogue: BN+relu, channel-major stores ----
  float* ob = out + (size_t)b*256*16384 + p0 + pt*16 + g;
#pragma unroll
  for(int nt=0;nt<16;++nt){
    int oc = oh*128+nt*8+2*tg;
    float2 sc=*(const float2*)(sb+oc), bi=*(const float2*)(bb+oc);
    ob[(size_t)oc*16384]       = fmaxf(fmaf(s2r[nt][0],sc.x,bi.x),0.f);
    ob[(size_t)(oc+1)*16384]   = fmaxf(fmaf(s2r[nt][1],sc.y,bi.y),0.f);
    ob[(size_t)oc*16384+8]     = fmaxf(fmaf(s2r[nt][2],sc.x,bi.x),0.f);
    ob[(size_t)(oc+1)*16384+8] = fmaxf(fmaf(s2r[nt][3],sc.y,bi.y),0.f);
  }
}

// ---------------------------------------------------------------------------
extern "C" void kernel_launch(void* const* d_in, const int* in_sizes, int n_in,
                              void* d_out, int out_size)
{
  const float* qfeat=(const float*)d_in[0];
  const float* kfeat=(const float*)d_in[1];
  const float* vfeat=(const float*)d_in[2];
  const int*   kmask=(const int*)d_in[3];
  const float* Wq1=(const float*)d_in[4];  const float* sq1=(const float*)d_in[5];  const float* bq1=(const float*)d_in[6];
  const float* Wq2=(const float*)d_in[7];  const float* sq2=(const float*)d_in[8];  const float* bq2=(const float*)d_in[9];
  const float* Wk1=(const float*)d_in[10]; const float* sk1=(const float*)d_in[11]; const float* bk1=(const float*)d_in[12];
  const float* Wk2=(const float*)d_in[13]; const float* sk2=(const float*)d_in[14]; const float* bk2=(const float*)d_in[15];
  const float* Wv =(const float*)d_in[16]; const float* sv =(const float*)d_in[17]; const float* bv =(const float*)d_in[18];
  const float* Wo =(const float*)d_in[19]; const float* so =(const float*)d_in[20]; const float* bo =(const float*)d_in[21];
  const float* Wb =(const float*)d_in[22]; const float* sb =(const float*)d_in[23]; const float* bb =(const float*)d_in[24];

  float *gq,*gk,*gv,*gc;
  cudaGetSymbolAddress((void**)&gq, g_q);
  cudaGetSymbolAddress((void**)&gk, g_k);
  cudaGetSymbolAddress((void**)&gv, g_v);
  cudaGetSymbolAddress((void**)&gc, g_ctx);

  const int SP = (64*132 + 128*132)*4;                 // 101,376 B (2 CTAs/SM)
  const int SA = (128*132 + 32*132 + 32*136 + 1024)*4; // 105,984 B (2 CTAs/SM)
  const int SO = (64*260 + 256*36)*4;                  // 103,424 B (2 CTAs/SM)
  cudaFuncSetAttribute(proj_kernel<true >, cudaFuncAttributeMaxDynamicSharedMemorySize, SP);
  cudaFuncSetAttribute(proj_kernel<false>, cudaFuncAttributeMaxDynamicSharedMemorySize, SP);
  cudaFuncSetAttribute(attn_kernel,        cudaFuncAttributeMaxDynamicSharedMemorySize, SA);
  cudaFuncSetAttribute(out_kernel,         cudaFuncAttributeMaxDynamicSharedMemorySize, SO);

  proj_kernel<true ><<<dim3(256,4),256,SP>>>(qfeat,16384,Wq1,sq1,bq1,Wq2,sq2,bq2,gq);
  proj_kernel<true ><<<dim3(16, 4),256,SP>>>(kfeat,1024, Wk1,sk1,bk1,Wk2,sk2,bk2,gk);
  proj_kernel<false><<<dim3(16, 4),256,SP>>>(vfeat,1024, Wv, sv, bv, nullptr,nullptr,nullptr,gv);
  attn_kernel<<<dim3(128,4),256,SA>>>(gq,gk,gv,kmask,gc);
  out_kernel <<<dim3(256,4),256,SO>>>(gc,qfeat,Wo,so,bo,Wb,sb,bb,(float*)d_out);
}

// round 17
// speedup vs baseline: 3.6965x; 1.2330x over previous
#include <cuda_runtime.h>
#include <cuda_fp16.h>
#include <cstdint>

#define SCALE 0.08838834764831845f
#define NEGV  -10000000.0f

// scratch (device globals -- no allocation allowed)
__device__ __half g_q  [4L*16384*128];  // [B][HW][C] pixel-major fp16
__device__ __half g_k  [4L*1024*128];   // [B][K][C]  pixel-major fp16
__device__ __half g_v  [4L*128*1024];   // [B][C][K]  channel-major fp16 (V^T)
__device__ float  g_ctx[4L*16384*128];  // [B][HW][C] fp32

// ---------------- mma helpers ----------------------------------------------
__device__ __forceinline__ void mma_tf32(float c[4],
    uint32_t a0, uint32_t a1, uint32_t a2, uint32_t a3, uint32_t b0, uint32_t b1){
  asm volatile(
    "mma.sync.aligned.m16n8k8.row.col.f32.tf32.tf32.f32 "
    "{%0,%1,%2,%3}, {%4,%5,%6,%7}, {%8,%9}, {%0,%1,%2,%3};\n"
    : "+f"(c[0]),"+f"(c[1]),"+f"(c[2]),"+f"(c[3])
    : "r"(a0),"r"(a1),"r"(a2),"r"(a3),"r"(b0),"r"(b1));
}
__device__ __forceinline__ void mma_f16(float c[4],
    uint32_t a0, uint32_t a1, uint32_t a2, uint32_t a3, uint32_t b0, uint32_t b1){
  asm volatile(
    "mma.sync.aligned.m16n8k16.row.col.f32.f16.f16.f32 "
    "{%0,%1,%2,%3}, {%4,%5,%6,%7}, {%8,%9}, {%0,%1,%2,%3};\n"
    : "+f"(c[0]),"+f"(c[1]),"+f"(c[2]),"+f"(c[3])
    : "r"(a0),"r"(a1),"r"(a2),"r"(a3),"r"(b0),"r"(b1));
}
__device__ __forceinline__ uint32_t f2tf(float x){
  uint32_t r; asm("cvt.rna.tf32.f32 %0, %1;" : "=r"(r) : "f"(x)); return r;
}
__device__ __forceinline__ void tfsplit(float x, uint32_t& h, uint32_t& l){
  h = f2tf(x); l = __float_as_uint(x - __uint_as_float(h));
}
__device__ __forceinline__ uint32_t pk2h(float a, float b){
  __half2 h = __floats2half2_rn(a,b);
  return *reinterpret_cast<uint32_t*>(&h);
}

// ---------------------------------------------------------------------------
// proj: (1|2) x [1x1 conv+BN+ReLU] on tf32 MMA, fp16 output.
// TOUT=true: channel-major output (for V). 64 pixels/CTA, 2 CTAs/SM.
// ---------------------------------------------------------------------------
template<bool TWO, bool TOUT>
__global__ __launch_bounds__(256,2) void proj_kernel(
    const float* __restrict__ in, int NP,
    const float* __restrict__ W1, const float* __restrict__ s1, const float* __restrict__ b1,
    const float* __restrict__ W2, const float* __restrict__ s2, const float* __restrict__ b2,
    __half* __restrict__ out)
{
  extern __shared__ float sm[];
  float* xs = sm;            // [64][132]
  float* ws = sm + 64*132;   // [128][132]
  const int tid=threadIdx.x, lane=tid&31, w=tid>>5;
  const int g=lane>>2, tg=lane&3;
  const int b=blockIdx.y, p0=blockIdx.x*64;
  const int pt=w&3, oh=w>>2;

  { const float4* W14=(const float4*)W1; float4* d=(float4*)ws;
    for(int i=tid;i<4096;i+=256){ int o=i>>5,c4=i&31; d[o*33+c4]=W14[i]; } }
  { const float* base = in + (size_t)b*128*NP + p0;
    for (int i=tid;i<2048;i+=256){
      int c = i>>4, p4 = (i&15)<<2;
      float4 v = *(const float4*)(base + (size_t)c*NP + p4);
      xs[(p4+0)*132+c]=v.x; xs[(p4+1)*132+c]=v.y;
      xs[(p4+2)*132+c]=v.z; xs[(p4+3)*132+c]=v.w;
    } }
  __syncthreads();

  float acc[8][4];
#pragma unroll
  for(int nt=0;nt<8;++nt){acc[nt][0]=0.f;acc[nt][1]=0.f;acc[nt][2]=0.f;acc[nt][3]=0.f;}
#pragma unroll
  for(int kk=0;kk<16;++kk){
    const float* qa = xs + (pt*16+g)*132 + kk*8 + tg;
    uint32_t a0=f2tf(qa[0]), a1=f2tf(qa[8*132]), a2=f2tf(qa[4]), a3=f2tf(qa[8*132+4]);
#pragma unroll
    for(int nt=0;nt<8;++nt){
      const float* wb = ws + (oh*64+nt*8+g)*132 + kk*8 + tg;
      mma_tf32(acc[nt], a0,a1,a2,a3, f2tf(wb[0]), f2tf(wb[4]));
    }
  }
  __syncthreads();

  if (TWO) {
#pragma unroll
    for(int nt=0;nt<8;++nt){
      int oc = oh*64+nt*8+2*tg;
      float2 sc=*(const float2*)(s1+oc), bi=*(const float2*)(b1+oc);
      float* c0 = xs + (pt*16+g)*132 + oc;
      float* c1 = xs + (pt*16+g+8)*132 + oc;
      c0[0]=fmaxf(fmaf(acc[nt][0],sc.x,bi.x),0.f);
      c0[1]=fmaxf(fmaf(acc[nt][1],sc.y,bi.y),0.f);
      c1[0]=fmaxf(fmaf(acc[nt][2],sc.x,bi.x),0.f);
      c1[1]=fmaxf(fmaf(acc[nt][3],sc.y,bi.y),0.f);
    }
    { const float4* W24=(const float4*)W2; float4* d=(float4*)ws;
      for(int i=tid;i<4096;i+=256){ int o=i>>5,c4=i&31; d[o*33+c4]=W24[i]; } }
    __syncthreads();
#pragma unroll
    for(int nt=0;nt<8;++nt){acc[nt][0]=0.f;acc[nt][1]=0.f;acc[nt][2]=0.f;acc[nt][3]=0.f;}
#pragma unroll
    for(int kk=0;kk<16;++kk){
      const float* qa = xs + (pt*16+g)*132 + kk*8 + tg;
      uint32_t a0=f2tf(qa[0]), a1=f2tf(qa[8*132]), a2=f2tf(qa[4]), a3=f2tf(qa[8*132+4]);
#pragma unroll
      for(int nt=0;nt<8;++nt){
        const float* wb = ws + (oh*64+nt*8+g)*132 + kk*8 + tg;
        mma_tf32(acc[nt], a0,a1,a2,a3, f2tf(wb[0]), f2tf(wb[4]));
      }
    }
  }
  const float* ss = TWO ? s2 : s1;
  const float* bs = TWO ? b2 : b1;
  if (TOUT) {   // channel-major half: out[oc][p]
    __half* ob = out + (size_t)b*128*NP + p0 + pt*16 + g;
#pragma unroll
    for(int nt=0;nt<8;++nt){
      int oc = oh*64+nt*8+2*tg;
      float2 sc=*(const float2*)(ss+oc), bi=*(const float2*)(bs+oc);
      ob[(size_t)oc*NP]       = __float2half(fmaxf(fmaf(acc[nt][0],sc.x,bi.x),0.f));
      ob[(size_t)(oc+1)*NP]   = __float2half(fmaxf(fmaf(acc[nt][1],sc.y,bi.y),0.f));
      ob[(size_t)oc*NP+8]     = __float2half(fmaxf(fmaf(acc[nt][2],sc.x,bi.x),0.f));
      ob[(size_t)(oc+1)*NP+8] = __float2half(fmaxf(fmaf(acc[nt][3],sc.y,bi.y),0.f));
    }
  } else {      // pixel-major half: out[p][oc]
    __half* o0 = out + ((size_t)b*NP + p0 + pt*16 + g)*128;
    __half* o1 = o0 + 8*128;
#pragma unroll
    for(int nt=0;nt<8;++nt){
      int oc = oh*64+nt*8+2*tg;
      float2 sc=*(const float2*)(ss+oc), bi=*(const float2*)(bs+oc);
      *(__half2*)(o0+oc) = __floats2half2_rn(fmaxf(fmaf(acc[nt][0],sc.x,bi.x),0.f),
                                             fmaxf(fmaf(acc[nt][1],sc.y,bi.y),0.f));
      *(__half2*)(o1+oc) = __floats2half2_rn(fmaxf(fmaf(acc[nt][2],sc.x,bi.x),0.f),
                                             fmaxf(fmaf(acc[nt][3],sc.y,bi.y),0.f));
    }
  }
}

// ---------------------------------------------------------------------------
// Flash attention on mma.sync m16n8k16 fp16 (fp32 accum).
// CTA: 256 thr = 8 warps, 128 queries (16/warp). K in 32 chunks of 32.
// P: QK C-frag pairs ARE the fp16 A-frag words -> zero-shuffle transpose.
// smem 57.9KB, 2 CTAs/SM (128 regs).
// ---------------------------------------------------------------------------
__global__ __launch_bounds__(256,2) void attn_kernel(
    const __half* __restrict__ q, const __half* __restrict__ k,
    const __half* __restrict__ vt, const int* __restrict__ mask,
    float* __restrict__ ctx)
{
  extern __shared__ uint32_t smw[];
  uint32_t* qs = smw;                 // [128][68] half2-words (pitch 68 = 4 mod 32)
  uint32_t* ks = smw + 128*68;        // [32][68]
  uint32_t* vs = smw + 128*68+32*68;  // [128 ch][20] words (pitch 20 -> banks 20g+tg distinct)
  float* msk   = (float*)(smw + 128*68+32*68+128*20); // [1024] bias 0/NEGV
  const int tid=threadIdx.x, lane=tid&31, w=tid>>5;
  const int g=lane>>2, tg=lane&3;
  const int b=blockIdx.y, q0=blockIdx.x*128, qb=w*16;

  { const int4* qg=(const int4*)(q + ((size_t)b*16384 + q0)*128);
    for(int i=tid;i<2048;i+=256){ int r=i>>4, sg=i&15; *(int4*)(qs + r*68 + sg*4) = qg[i]; } }
  for(int i=tid;i<1024;i+=256) msk[i] = mask[b*1024+i] ? 0.f : NEGV;

  float m0=-3.0e38f,m1=-3.0e38f,l0=0.f,l1=0.f;
  float o[16][4];
#pragma unroll
  for(int nt=0;nt<16;++nt){o[nt][0]=0.f;o[nt][1]=0.f;o[nt][2]=0.f;o[nt][3]=0.f;}

  const int4* kgb=(const int4*)(k + (size_t)b*1024*128);
  const int4* vgb=(const int4*)(vt + (size_t)b*131072);

  for(int kb=0;kb<32;++kb){
    const int j0=kb*32;
    __syncthreads();
    for(int i=tid;i<512;i+=256){   // K chunk: 32 keys x 128c
      int r=i>>4, sg=i&15;
      *(int4*)(ks + r*68 + sg*4) = kgb[(size_t)(j0+r)*16 + sg];
    }
    for(int i=tid+256;i<768;i+=256){}  // (keep thread count balanced; no-op)
    for(int i=tid;i<512;i+=256){   // V^T chunk: 128c x 32 keys
      int c=i>>2, sg=i&3;
      *(int4*)(vs + c*20 + sg*4) = vgb[c*128 + kb*4 + sg];
    }
    __syncthreads();

    // ---- S = Q K^T  (16 q x 32 keys / warp), k16 fp16 ----
    float s[4][4];
#pragma unroll
    for(int nt=0;nt<4;++nt){s[nt][0]=0.f;s[nt][1]=0.f;s[nt][2]=0.f;s[nt][3]=0.f;}
#pragma unroll
    for(int kk=0;kk<8;++kk){
      const uint32_t* qa = qs + (qb+g)*68 + kk*8 + tg;
      uint32_t a0=qa[0], a1=qa[8*68], a2=qa[4], a3=qa[8*68+4];
#pragma unroll
      for(int nt=0;nt<4;++nt){
        const uint32_t* kp = ks + (nt*8+g)*68 + kk*8 + tg;
        mma_f16(s[nt], a0,a1,a2,a3, kp[0], kp[4]);
      }
    }
    // ---- mask bias + scale + online softmax ----
    float mx0=-3.0e38f, mx1=-3.0e38f;
#pragma unroll
    for(int nt=0;nt<4;++nt){
      float2 bi = *(const float2*)(msk + j0 + nt*8 + 2*tg);
      s[nt][0]=fmaf(s[nt][0],SCALE,bi.x);
      s[nt][1]=fmaf(s[nt][1],SCALE,bi.y);
      s[nt][2]=fmaf(s[nt][2],SCALE,bi.x);
      s[nt][3]=fmaf(s[nt][3],SCALE,bi.y);
      mx0=fmaxf(mx0,fmaxf(s[nt][0],s[nt][1]));
      mx1=fmaxf(mx1,fmaxf(s[nt][2],s[nt][3]));
    }
    mx0=fmaxf(mx0,__shfl_xor_sync(0xffffffffu,mx0,1));
    mx0=fmaxf(mx0,__shfl_xor_sync(0xffffffffu,mx0,2));
    mx1=fmaxf(mx1,__shfl_xor_sync(0xffffffffu,mx1,1));
    mx1=fmaxf(mx1,__shfl_xor_sync(0xffffffffu,mx1,2));
    float mn0=fmaxf(m0,mx0), mn1=fmaxf(m1,mx1);
    float al0=__expf(m0-mn0), al1=__expf(m1-mn1);
    m0=mn0; m1=mn1;
    float ls0=0.f, ls1=0.f;
#pragma unroll
    for(int nt=0;nt<4;++nt){
      s[nt][0]=__expf(s[nt][0]-m0); s[nt][1]=__expf(s[nt][1]-m0);
      s[nt][2]=__expf(s[nt][2]-m1); s[nt][3]=__expf(s[nt][3]-m1);
      ls0+=s[nt][0]+s[nt][1]; ls1+=s[nt][2]+s[nt][3];
    }
    ls0+=__shfl_xor_sync(0xffffffffu,ls0,1); ls0+=__shfl_xor_sync(0xffffffffu,ls0,2);
    ls1+=__shfl_xor_sync(0xffffffffu,ls1,1); ls1+=__shfl_xor_sync(0xffffffffu,ls1,2);
    l0=l0*al0+ls0; l1=l1*al1+ls1;
#pragma unroll
    for(int nt=0;nt<16;++nt){ o[nt][0]*=al0; o[nt][1]*=al0; o[nt][2]*=al1; o[nt][3]*=al1; }

    // ---- ctx += P V : C-frag pairs pack directly into fp16 A-frags ----
#pragma unroll
    for(int G=0;G<2;++G){
      uint32_t a0 = pk2h(s[2*G  ][0], s[2*G  ][1]);   // P[g   ][2tg..+1] keys G*16+
      uint32_t a1 = pk2h(s[2*G  ][2], s[2*G  ][3]);   // P[g+8 ][2tg..+1]
      uint32_t a2 = pk2h(s[2*G+1][0], s[2*G+1][1]);   // P[g   ][2tg+8..+9]
      uint32_t a3 = pk2h(s[2*G+1][2], s[2*G+1][3]);   // P[g+8 ][2tg+8..+9]
#pragma unroll
      for(int nt=0;nt<16;++nt){
        const uint32_t* vb = vs + (nt*8+g)*20 + G*8 + tg;
        mma_f16(o[nt], a0,a1,a2,a3, vb[0], vb[4]);
      }
    }
  }
  const float inv0=1.f/l0, inv1=1.f/l1;
  float* og0 = ctx + ((size_t)b*16384 + q0 + qb + g)*128;
  float* og1 = og0 + 8*128;
#pragma unroll
  for(int nt=0;nt<16;++nt){
    *(float2*)(og0 + nt*8+2*tg) = make_float2(o[nt][0]*inv0, o[nt][1]*inv0);
    *(float2*)(og1 + nt*8+2*tg) = make_float2(o[nt][2]*inv1, o[nt][3]*inv1);
  }
}

// ---------------------------------------------------------------------------
// Fused out_project + bottleneck on 3-term tf32 MMA (~fp32). (unchanged)
// ---------------------------------------------------------------------------
__global__ __launch_bounds__(256,2) void out_kernel(
    const float* __restrict__ ctxin, const float* __restrict__ qf,
    const float* __restrict__ Wo, const float* __restrict__ so, const float* __restrict__ bo,
    const float* __restrict__ Wb, const float* __restrict__ sb, const float* __restrict__ bb,
    float* __restrict__ out)
{
  extern __shared__ float sm[];
  float* cat = sm;             // [64][260]
  float* ws  = cat + 64*260;   // [256][36]
  const int tid=threadIdx.x, lane=tid&31, w=tid>>5;
  const int g=lane>>2, tg=lane&3;
  const int b=blockIdx.y, p0=blockIdx.x*64;
  const int pt=w&3, oh=w>>2;

  { const float* base = qf + (size_t)b*128*16384 + p0;
    for(int i=tid;i<2048;i+=256){
      int c=i>>4, p4=(i&15)<<2;
      float4 v=*(const float4*)(base + (size_t)c*16384 + p4);
      cat[(p4+0)*260+128+c]=v.x; cat[(p4+1)*260+128+c]=v.y;
      cat[(p4+2)*260+128+c]=v.z; cat[(p4+3)*260+128+c]=v.w;
    } }

  float s1r[8][4];
#pragma unroll
  for(int nt=0;nt<8;++nt){s1r[nt][0]=0.f;s1r[nt][1]=0.f;s1r[nt][2]=0.f;s1r[nt][3]=0.f;}
  const float* actx = ctxin + ((size_t)b*16384 + p0 + pt*16 + g)*128;
  for(int cb=0;cb<4;++cb){
    __syncthreads();
    { const float4* W4=(const float4*)Wo; float4* d=(float4*)ws;
      for(int i=tid;i<1024;i+=256){ int o=i>>3,c4=i&7; d[o*9+c4]=W4[o*32 + cb*8 + c4]; } }
    __syncthreads();
#pragma unroll
    for(int kk=0;kk<4;++kk){
      int co = cb*32 + kk*8 + tg;
      uint32_t ah0,al0,ah1,al1,ah2,al2,ah3,al3;
      tfsplit(__ldg(actx + co),             ah0,al0);
      tfsplit(__ldg(actx + 8*128 + co),     ah1,al1);
      tfsplit(__ldg(actx + co + 4),         ah2,al2);
      tfsplit(__ldg(actx + 8*128 + co + 4), ah3,al3);
#pragma unroll
      for(int nt=0;nt<8;++nt){
        const float* wb = ws + (oh*64+nt*8+g)*36 + kk*8 + tg;
        uint32_t bh0,bl0,bh1,bl1;
        tfsplit(wb[0], bh0,bl0); tfsplit(wb[4], bh1,bl1);
        mma_tf32(s1r[nt], ah0,ah1,ah2,ah3, bh0,bh1);
        mma_tf32(s1r[nt], al0,al1,al2,al3, bh0,bh1);
        mma_tf32(s1r[nt], ah0,ah1,ah2,ah3, bl0,bl1);
      }
    }
  }
#pragma unroll
  for(int nt=0;nt<8;++nt){
    int oc = oh*64+nt*8+2*tg;
    float2 sc=*(const float2*)(so+oc), bi=*(const float2*)(bo+oc);
    float* c0 = cat + (pt*16+g)*260 + oc;
    float* c1 = cat + (pt*16+g+8)*260 + oc;
    c0[0]=fmaxf(fmaf(s1r[nt][0],sc.x,bi.x),0.f);
    c0[1]=fmaxf(fmaf(s1r[nt][1],sc.y,bi.y),0.f);
    c1[0]=fmaxf(fmaf(s1r[nt][2],sc.x,bi.x),0.f);
    c1[1]=fmaxf(fmaf(s1r[nt][3],sc.y,bi.y),0.f);
  }

  float s2r[16][4];
#pragma unroll
  for(int nt=0;nt<16;++nt){s2r[nt][0]=0.f;s2r[nt][1]=0.f;s2r[nt][2]=0.f;s2r[nt][3]=0.f;}
  for(int cb=0;cb<8;++cb){
    __syncthreads();
    { const float4* W4=(const float4*)Wb; float4* d=(float4*)ws;
      for(int i=tid;i<2048;i+=256){ int o=i>>3,c4=i&7; d[o*9+c4]=W4[o*64 + cb*8 + c4]; } }
    __syncthreads();
#pragma unroll
    for(int kk=0;kk<4;++kk){
      const float* qa = cat + (pt*16+g)*260 + cb*32 + kk*8 + tg;
      uint32_t ah0,al0,ah1,al1,ah2,al2,ah3,al3;
      tfsplit(qa[0],       ah0,al0);
      tfsplit(qa[8*260],   ah1,al1);
      tfsplit(qa[4],       ah2,al2);
      tfsplit(qa[8*260+4], ah3,al3);
#pragma unroll
      for(int nt=0;nt<16;++nt){
        const float* wb = ws + (oh*128+nt*8+g)*36 + kk*8 + tg;
        uint32_t bh0,bl0,bh1,bl1;
        tfsplit(wb[0], bh0,bl0); tfsplit(wb[4], bh1,bl1);
        mma_tf32(s2r[nt], ah0,ah1,ah2,ah3, bh0,bh1);
        mma_tf32(s2r[nt], al0,al1,al2,al3, bh0,bh1);
        mma_tf32(s2r[nt], ah0,ah1,ah2,ah3, bl0,bl1);
      }
    }
  }
  float* ob = out + (size_t)b*256*16384 + p0 + pt*16 + g;
#pragma unroll
  for(int nt=0;nt<16;++nt){
    int oc = oh*128+nt*8+2*tg;
    float2 sc=*(const float2*)(sb+oc), bi=*(const float2*)(bb+oc);
    ob[(size_t)oc*16384]       = fmaxf(fmaf(s2r[nt][0],sc.x,bi.x),0.f);
    ob[(size_t)(oc+1)*16384]   = fmaxf(fmaf(s2r[nt][1],sc.y,bi.y),0.f);
    ob[(size_t)oc*16384+8]     = fmaxf(fmaf(s2r[nt][2],sc.x,bi.x),0.f);
    ob[(size_t)(oc+1)*16384+8] = fmaxf(fmaf(s2r[nt][3],sc.y,bi.y),0.f);
  }
}

// ---------------------------------------------------------------------------
extern "C" void kernel_launch(void* const* d_in, const int* in_sizes, int n_in,
                              void* d_out, int out_size)
{
  const float* qfeat=(const float*)d_in[0];
  const float* kfeat=(const float*)d_in[1];
  const float* vfeat=(const float*)d_in[2];
  const int*   kmask=(const int*)d_in[3];
  const float* Wq1=(const float*)d_in[4];  const float* sq1=(const float*)d_in[5];  const float* bq1=(const float*)d_in[6];
  const float* Wq2=(const float*)d_in[7];  const float* sq2=(const float*)d_in[8];  const float* bq2=(const float*)d_in[9];
  const float* Wk1=(const float*)d_in[10]; const float* sk1=(const float*)d_in[11]; const float* bk1=(const float*)d_in[12];
  const float* Wk2=(const float*)d_in[13]; const float* sk2=(const float*)d_in[14]; const float* bk2=(const float*)d_in[15];
  const float* Wv =(const float*)d_in[16]; const float* sv =(const float*)d_in[17]; const float* bv =(const float*)d_in[18];
  const float* Wo =(const float*)d_in[19]; const float* so =(const float*)d_in[20]; const float* bo =(const float*)d_in[21];
  const float* Wb =(const float*)d_in[22]; const float* sb =(const float*)d_in[23]; const float* bb =(const float*)d_in[24];

  __half *gq,*gk,*gv; float *gc;
  cudaGetSymbolAddress((void**)&gq, g_q);
  cudaGetSymbolAddress((void**)&gk, g_k);
  cudaGetSymbolAddress((void**)&gv, g_v);
  cudaGetSymbolAddress((void**)&gc, g_ctx);

  const int SP = (64*132 + 128*132)*4;                      // 101,376 B
  const int SA = (128*68 + 32*68 + 128*20)*4 + 1024*4;      //  57,856 B
  const int SO = (64*260 + 256*36)*4;                       // 103,424 B
  cudaFuncSetAttribute(proj_kernel<true ,false>, cudaFuncAttributeMaxDynamicSharedMemorySize, SP);
  cudaFuncSetAttribute(proj_kernel<false,true >, cudaFuncAttributeMaxDynamicSharedMemorySize, SP);
  cudaFuncSetAttribute(attn_kernel,              cudaFuncAttributeMaxDynamicSharedMemorySize, SA);
  cudaFuncSetAttribute(out_kernel,               cudaFuncAttributeMaxDynamicSharedMemorySize, SO);

  proj_kernel<true ,false><<<dim3(256,4),256,SP>>>(qfeat,16384,Wq1,sq1,bq1,Wq2,sq2,bq2,gq);
  proj_kernel<true ,false><<<dim3(16, 4),256,SP>>>(kfeat,1024, Wk1,sk1,bk1,Wk2,sk2,bk2,gk);
  proj_kernel<false,true ><<<dim3(16, 4),256,SP>>>(vfeat,1024, Wv, sv, bv, nullptr,nullptr,nullptr,gv);
  attn_kernel<<<dim3(128,4),256,SA>>>(gq,gk,gv,kmask,gc);
  out_kernel <<<dim3(256,4),256,SO>>>(gc,qfeat,Wo,so,bo,Wb,sb,bb,(float*)d_out);
}